// round 5
// baseline (speedup 1.0000x reference)
#include <cuda_runtime.h>
#include <math.h>

#define Bq  4
#define SEQ 2048
#define CH  768
#define NH  12
#define HD  64
#define NTOK (Bq * SEQ)

#define QT  256     // q rows per CTA
#define KB  32      // keys per block
#define KC  16      // k-dim chunk

// NO __device__ globals in this version: the only writable memory is d_out.

__global__ void bias_init_kernel(const float* __restrict__ bias,
                                 float* __restrict__ out, int n) {
    int i = blockIdx.x * blockDim.x + threadIdx.x;
    if (i < n) out[i] = bias[i % CH];
}

// One CTA = (q-tile of 256 rows, one (b,h)). Thread t owns q row t entirely.
// Computes Q,K,V projections on the fly from x and qkv_w (head-sliced), runs
// online-softmax attention, then accumulates this head's contribution to the
// final projection directly into out via atomicAdd.
__global__ __launch_bounds__(256) void fused_attn_kernel(
    const float* __restrict__ x,      // (4,2048,768)
    const float* __restrict__ w,      // qkv_w (2304,768)
    const float* __restrict__ pw,     // proj_w (768,768)
    float* __restrict__ out)          // (4,2048,768), pre-filled with bias
{
    __shared__ __align__(16) float sm[7072];
    // KV-phase layout (floats):
    float* Ks  = sm;            // [KB][68]  = 2176
    float* Vs  = sm + 2176;     // [KB][68]  = 2176
    float* xs  = sm + 4352;     // [KC][34]  = 544
    float* wks = sm + 4896;     // [KC][68]  = 1088
    float* wvs = sm + 5984;     // [KC][68]  = 1088
    // Q-phase overlay (dead before first K/V write):
    float* xq  = sm;            // [KC][257] = 4112
    float* wqs = sm + 4112;     // [KC][68]  = 1088
    // proj-phase overlay (after attention):
    float* ws  = sm;            // [64][68]  = 4352

    int tid = threadIdx.x;
    int bh = blockIdx.y;
    int b = bh / NH, h = bh % NH;
    int q0 = blockIdx.x * QT;

    // ---- Phase 1: Q tile (row t in registers), scaled by hd^-0.5 ----
    float qreg[HD];
#pragma unroll
    for (int d = 0; d < HD; d++) qreg[d] = 0.f;

    for (int k0 = 0; k0 < CH; k0 += KC) {
#pragma unroll
        for (int i = 0; i < 16; i++) {
            int e = tid + 256 * i;
            int r = e >> 4, kk = e & 15;
            xq[kk * 257 + r] = x[(b * SEQ + q0 + r) * CH + k0 + kk];
        }
#pragma unroll
        for (int i = 0; i < 4; i++) {
            int e = tid + 256 * i;
            int d = e >> 4, kk = e & 15;
            wqs[kk * 68 + d] = w[(h * HD + d) * CH + k0 + kk];
        }
        __syncthreads();
#pragma unroll
        for (int kk = 0; kk < KC; kk++) {
            float xv = xq[kk * 257 + tid];
#pragma unroll
            for (int dd = 0; dd < 16; dd++) {
                float4 w4 = *(const float4*)&wqs[kk * 68 + 4 * dd];
                qreg[4 * dd + 0] += xv * w4.x;
                qreg[4 * dd + 1] += xv * w4.y;
                qreg[4 * dd + 2] += xv * w4.z;
                qreg[4 * dd + 3] += xv * w4.w;
            }
        }
        __syncthreads();
    }
#pragma unroll
    for (int d = 0; d < HD; d++) qreg[d] *= 0.125f;

    // ---- Phase 2: stream keys, online softmax ----
    float m = -1e30f, l = 0.f;
    float oreg[HD];
#pragma unroll
    for (int d = 0; d < HD; d++) oreg[d] = 0.f;

    int ry = tid >> 4;   // 0..15 -> K/V rows {2ry, 2ry+1}
    int cx = tid & 15;   // cols {4cx .. 4cx+3}

    for (int kb = 0; kb < SEQ; kb += KB) {
        // K/V projection for this 32-key block (accumulate in regs)
        float kacc[2][4], vacc[2][4];
#pragma unroll
        for (int i = 0; i < 2; i++)
#pragma unroll
            for (int j = 0; j < 4; j++) { kacc[i][j] = 0.f; vacc[i][j] = 0.f; }

        for (int k0 = 0; k0 < CH; k0 += KC) {
#pragma unroll
            for (int i = 0; i < 2; i++) {
                int e = tid + 256 * i;
                int r = e >> 4, kk = e & 15;
                xs[kk * 34 + r] = x[(b * SEQ + kb + r) * CH + k0 + kk];
            }
#pragma unroll
            for (int i = 0; i < 4; i++) {
                int e = tid + 256 * i;
                int d = e >> 4, kk = e & 15;
                wks[kk * 68 + d] = w[(CH + h * HD + d) * CH + k0 + kk];
                wvs[kk * 68 + d] = w[(2 * CH + h * HD + d) * CH + k0 + kk];
            }
            __syncthreads();
#pragma unroll
            for (int kk = 0; kk < KC; kk++) {
                float2 xv = *(const float2*)&xs[kk * 34 + 2 * ry];
                float4 wk = *(const float4*)&wks[kk * 68 + 4 * cx];
                float4 wv = *(const float4*)&wvs[kk * 68 + 4 * cx];
                kacc[0][0] += xv.x * wk.x; kacc[0][1] += xv.x * wk.y;
                kacc[0][2] += xv.x * wk.z; kacc[0][3] += xv.x * wk.w;
                kacc[1][0] += xv.y * wk.x; kacc[1][1] += xv.y * wk.y;
                kacc[1][2] += xv.y * wk.z; kacc[1][3] += xv.y * wk.w;
                vacc[0][0] += xv.x * wv.x; vacc[0][1] += xv.x * wv.y;
                vacc[0][2] += xv.x * wv.z; vacc[0][3] += xv.x * wv.w;
                vacc[1][0] += xv.y * wv.x; vacc[1][1] += xv.y * wv.y;
                vacc[1][2] += xv.y * wv.z; vacc[1][3] += xv.y * wv.w;
            }
            __syncthreads();
        }
#pragma unroll
        for (int i = 0; i < 2; i++)
#pragma unroll
            for (int j = 0; j < 4; j++) {
                Ks[(2 * ry + i) * 68 + 4 * cx + j] = kacc[i][j];
                Vs[(2 * ry + i) * 68 + 4 * cx + j] = vacc[i][j];
            }
        __syncthreads();

        // S row (32 keys) for this thread's q row
        float sarr[KB];
#pragma unroll
        for (int j = 0; j < KB; j++) {
            float sj = 0.f;
#pragma unroll
            for (int dd = 0; dd < 16; dd++) {
                float4 k4 = *(const float4*)&Ks[j * 68 + 4 * dd];
                sj += qreg[4 * dd + 0] * k4.x + qreg[4 * dd + 1] * k4.y
                    + qreg[4 * dd + 2] * k4.z + qreg[4 * dd + 3] * k4.w;
            }
            sarr[j] = sj;
        }

        float mx = m;
#pragma unroll
        for (int j = 0; j < KB; j++) mx = fmaxf(mx, sarr[j]);
        float c = __expf(m - mx);
        m = mx;
        float sum = 0.f;
#pragma unroll
        for (int j = 0; j < KB; j++) {
            float pj = __expf(sarr[j] - mx);
            sarr[j] = pj;
            sum += pj;
        }
        l = l * c + sum;
#pragma unroll
        for (int d = 0; d < HD; d++) oreg[d] *= c;
#pragma unroll
        for (int j = 0; j < KB; j++) {
            float pj = sarr[j];
#pragma unroll
            for (int dd = 0; dd < 16; dd++) {
                float4 v4 = *(const float4*)&Vs[j * 68 + 4 * dd];
                oreg[4 * dd + 0] += pj * v4.x;
                oreg[4 * dd + 1] += pj * v4.y;
                oreg[4 * dd + 2] += pj * v4.z;
                oreg[4 * dd + 3] += pj * v4.w;
            }
        }
    }

    float inv = 1.0f / l;
#pragma unroll
    for (int d = 0; d < HD; d++) oreg[d] *= inv;

    // ---- Phase 3: project this head's slice and accumulate into out ----
    __syncthreads();   // all threads done reading Ks/Vs before ws overlays them
    float* orow = out + (b * SEQ + q0 + tid) * CH;
    for (int j0 = 0; j0 < CH; j0 += 64) {
#pragma unroll
        for (int i = 0; i < 16; i++) {
            int e = tid + 256 * i;
            int d = e & 63, jj = e >> 6;
            ws[jj * 68 + d] = pw[(j0 + jj) * CH + h * HD + d];
        }
        __syncthreads();
#pragma unroll 4
        for (int jj = 0; jj < 64; jj++) {
            float acc = 0.f;
#pragma unroll
            for (int dd = 0; dd < 16; dd++) {
                float4 w4 = *(const float4*)&ws[jj * 68 + 4 * dd];
                acc += oreg[4 * dd + 0] * w4.x + oreg[4 * dd + 1] * w4.y
                     + oreg[4 * dd + 2] * w4.z + oreg[4 * dd + 3] * w4.w;
            }
            atomicAdd(orow + j0 + jj, acc);
        }
        __syncthreads();
    }
}

// ---------------------------------------------------------------------------

extern "C" void kernel_launch(void* const* d_in, const int* in_sizes, int n_in,
                              void* d_out, int out_size) {
    const float* x = 0; const float* qkv_w = 0;
    const float* proj_w = 0; const float* proj_b = 0;
    for (int i = 0; i < n_in; i++) {
        int s = in_sizes[i];
        const float* p = (const float*)d_in[i];
        if (s == NTOK * CH)        { if (!x) x = p; }
        else if (s == 3 * CH * CH) { if (!qkv_w) qkv_w = p; }
        else if (s == CH * CH)     { if (!proj_w) proj_w = p; }
        else if (s == CH)          { if (!proj_b) proj_b = p; }
    }
    if (!x || !qkv_w || !proj_w || !proj_b) {
        x      = (const float*)d_in[0];
        qkv_w  = (const float*)d_in[1];
        proj_w = (const float*)d_in[2];
        proj_b = (const float*)d_in[3];
    }
    float* out = (float*)d_out;

    bias_init_kernel<<<(NTOK * CH + 255) / 256, 256>>>(proj_b, out, NTOK * CH);
    fused_attn_kernel<<<dim3(SEQ / QT, Bq * NH), 256>>>(x, qkv_w, proj_w, out);
}

// round 7
// speedup vs baseline: 3.2090x; 3.2090x over previous
#include <cuda_runtime.h>
#include <cuda_fp16.h>
#include <cstdint>
#include <math.h>

#define Bq  4
#define SEQ 2048
#define CH  768
#define NH  12
#define HD  64
#define NTOK (Bq * SEQ)

#define QT  256     // q rows per CTA
#define KB  32      // keys per block
#define KC  16      // k-dim chunk (Q phase)

#define WPAD  776   // wh row stride in halves (768 + 8 -> 16B stagger)
#define XPAD  72    // xh row stride in halves (64 + 8)
#define KVPAD 68    // Ks/Vs row stride in floats

// smem layout (bytes)
#define SZ_WH    (128 * WPAD * 2)            /* 198656 */
#define OFF_R    SZ_WH
#define OFF_XH0  (OFF_R)
#define OFF_XH1  (OFF_R + 32 * XPAD * 2)
#define OFF_KS   (OFF_R + 2 * 32 * XPAD * 2)
#define OFF_VS   (OFF_KS + KB * KVPAD * 4)
#define SMEM_TOTAL (OFF_VS + KB * KVPAD * 4) /* 225280 bytes */

__global__ void bias_init_kernel(const float* __restrict__ bias,
                                 float* __restrict__ out, int n) {
    int i = blockIdx.x * blockDim.x + threadIdx.x;
    if (i < n) out[i] = bias[i % CH];
}

__device__ __forceinline__ void ldm_x4(unsigned int* r, const void* p) {
    unsigned int a = (unsigned int)__cvta_generic_to_shared(p);
    asm volatile("ldmatrix.sync.aligned.m8n8.x4.shared.b16 {%0,%1,%2,%3}, [%4];"
                 : "=r"(r[0]), "=r"(r[1]), "=r"(r[2]), "=r"(r[3]) : "r"(a));
}
__device__ __forceinline__ void ldm_x2(unsigned int* r, const void* p) {
    unsigned int a = (unsigned int)__cvta_generic_to_shared(p);
    asm volatile("ldmatrix.sync.aligned.m8n8.x2.shared.b16 {%0,%1}, [%2];"
                 : "=r"(r[0]), "=r"(r[1]) : "r"(a));
}
__device__ __forceinline__ void mma16816(float* c, const unsigned int* a,
                                         const unsigned int* b) {
    asm volatile("mma.sync.aligned.m16n8k16.row.col.f32.f16.f16.f32 "
                 "{%0,%1,%2,%3},{%4,%5,%6,%7},{%8,%9},{%0,%1,%2,%3};"
                 : "+f"(c[0]), "+f"(c[1]), "+f"(c[2]), "+f"(c[3])
                 : "r"(a[0]), "r"(a[1]), "r"(a[2]), "r"(a[3]), "r"(b[0]), "r"(b[1]));
}

// One CTA = (q-tile of 256 rows, one (b,h)). Thread t owns q row t.
// K/V projection on tensor cores (fp16 mma, weights persisted in smem);
// Q proj, S, softmax, PV, out-proj as in the proven fp32 version.
__global__ __launch_bounds__(256) void fused_attn_kernel(
    const float* __restrict__ x,      // (4,2048,768)
    const float* __restrict__ w,      // qkv_w (2304,768)
    const float* __restrict__ pw,     // proj_w (768,768)
    float* __restrict__ out)          // (4,2048,768), pre-filled with bias
{
    extern __shared__ __align__(16) char smem[];
    half*  wh  = (half*)(smem);                  // [128][WPAD]: rows 0-63 wk, 64-127 wv
    float* Ks  = (float*)(smem + OFF_KS);        // [KB][KVPAD]
    float* Vs  = (float*)(smem + OFF_VS);        // [KB][KVPAD]
    float* xq  = (float*)(smem + OFF_R);         // Q-phase overlay [16][257]
    float* wqs = (float*)(smem + OFF_R + 16448); // [16][68]
    float* ws  = (float*)(smem + OFF_R);         // proj-phase overlay [64][68]

    int tid = threadIdx.x;
    int warp = tid >> 5, lane = tid & 31;
    int bh = blockIdx.y;
    int b = bh / NH, h = bh % NH;
    int q0 = blockIdx.x * QT;

    // ---- Stage K/V weights once: fp32 gmem -> fp16 smem ----
    for (int e = tid; e < 128 * 192; e += 256) {       // 192 float4 per row
        int n = e / 192, c4 = (e % 192) << 2;
        int grow = (n < 64) ? (CH + h * HD + n) : (2 * CH + h * HD + n - 64);
        float4 t = *(const float4*)&w[grow * CH + c4];
        half2* dst = (half2*)&wh[n * WPAD + c4];
        dst[0] = __floats2half2_rn(t.x, t.y);
        dst[1] = __floats2half2_rn(t.z, t.w);
    }

    // ---- Phase 1: Q tile (row tid in registers), scaled by hd^-0.5 ----
    float qreg[HD];
#pragma unroll
    for (int d = 0; d < HD; d++) qreg[d] = 0.f;

    for (int k0 = 0; k0 < CH; k0 += KC) {
        __syncthreads();
#pragma unroll
        for (int i = 0; i < 16; i++) {
            int e = tid + 256 * i;
            int r = e >> 4, kk = e & 15;
            xq[kk * 257 + r] = x[(b * SEQ + q0 + r) * CH + k0 + kk];
        }
#pragma unroll
        for (int i = 0; i < 4; i++) {
            int e = tid + 256 * i;
            int d = e >> 4, kk = e & 15;
            wqs[kk * 68 + d] = w[(h * HD + d) * CH + k0 + kk];
        }
        __syncthreads();
#pragma unroll
        for (int kk = 0; kk < KC; kk++) {
            float xv = xq[kk * 257 + tid];
#pragma unroll
            for (int dd = 0; dd < 16; dd++) {
                float4 w4 = *(const float4*)&wqs[kk * 68 + 4 * dd];
                qreg[4 * dd + 0] += xv * w4.x;
                qreg[4 * dd + 1] += xv * w4.y;
                qreg[4 * dd + 2] += xv * w4.z;
                qreg[4 * dd + 3] += xv * w4.w;
            }
        }
    }
    __syncthreads();
#pragma unroll
    for (int d = 0; d < HD; d++) qreg[d] *= 0.125f;

    // ---- Phase 2: stream keys; K/V projection on tensor cores ----
    float m = -1e30f, l = 0.f;
    float oreg[HD];
#pragma unroll
    for (int d = 0; d < HD; d++) oreg[d] = 0.f;

    for (int kb = 0; kb < SEQ; kb += KB) {
        // K/V tile GEMM: M=32 keys, N=128 (64 K-dims | 64 V-dims), K=768.
        float cfr[2][2][4];
#pragma unroll
        for (int mt = 0; mt < 2; mt++)
#pragma unroll
            for (int nt = 0; nt < 2; nt++)
#pragma unroll
                for (int qq = 0; qq < 4; qq++) cfr[mt][nt][qq] = 0.f;

        for (int ch = 0; ch < 12; ch++) {
            half* xh = (half*)(smem + ((ch & 1) ? OFF_XH1 : OFF_XH0));
#pragma unroll
            for (int r2 = 0; r2 < 2; r2++) {
                int e = tid + 256 * r2;              // 0..511
                int row = e >> 4, cg = (e & 15) << 2;
                float4 t = *(const float4*)&x[(b * SEQ + kb + row) * CH + ch * 64 + cg];
                half2* dst = (half2*)&xh[row * XPAD + cg];
                dst[0] = __floats2half2_rn(t.x, t.y);
                dst[1] = __floats2half2_rn(t.z, t.w);
            }
            __syncthreads();
#pragma unroll
            for (int ks = 0; ks < 4; ks++) {
                int kk = ks * 16;
                unsigned int afr[2][4], bfr[2][2];
#pragma unroll
                for (int mt = 0; mt < 2; mt++)
                    ldm_x4(afr[mt], &xh[(mt * 16 + (lane & 15)) * XPAD + kk + ((lane >> 4) << 3)]);
#pragma unroll
                for (int nt = 0; nt < 2; nt++) {
                    int l16 = lane & 15;
                    int row = warp * 16 + nt * 8 + (l16 & 7);
                    int kcol = ch * 64 + kk + ((l16 >> 3) << 3);
                    ldm_x2(bfr[nt], &wh[row * WPAD + kcol]);
                }
#pragma unroll
                for (int mt = 0; mt < 2; mt++)
#pragma unroll
                    for (int nt = 0; nt < 2; nt++)
                        mma16816(cfr[mt][nt], afr[mt], bfr[nt]);
            }
        }
        // Epilogue: fragments -> Ks/Vs (fp32)
        {
            float* dst = (warp < 4) ? Ks : Vs;
            int dim0 = (warp & 3) * 16;
            int gr = lane >> 2, gc = (lane & 3) << 1;
#pragma unroll
            for (int mt = 0; mt < 2; mt++)
#pragma unroll
                for (int nt = 0; nt < 2; nt++) {
                    int key = mt * 16 + gr;
                    int dim = dim0 + nt * 8 + gc;
                    dst[key * KVPAD + dim]           = cfr[mt][nt][0];
                    dst[key * KVPAD + dim + 1]       = cfr[mt][nt][1];
                    dst[(key + 8) * KVPAD + dim]     = cfr[mt][nt][2];
                    dst[(key + 8) * KVPAD + dim + 1] = cfr[mt][nt][3];
                }
        }
        __syncthreads();

        // S row (32 keys) for this thread's q row
        float sarr[KB];
#pragma unroll
        for (int j = 0; j < KB; j++) {
            float sj = 0.f;
#pragma unroll
            for (int dd = 0; dd < 16; dd++) {
                float4 k4 = *(const float4*)&Ks[j * KVPAD + 4 * dd];
                sj += qreg[4 * dd + 0] * k4.x + qreg[4 * dd + 1] * k4.y
                    + qreg[4 * dd + 2] * k4.z + qreg[4 * dd + 3] * k4.w;
            }
            sarr[j] = sj;
        }

        float mx = m;
#pragma unroll
        for (int j = 0; j < KB; j++) mx = fmaxf(mx, sarr[j]);
        float c = __expf(m - mx);
        m = mx;
        float sum = 0.f;
#pragma unroll
        for (int j = 0; j < KB; j++) {
            float pj = __expf(sarr[j] - mx);
            sarr[j] = pj;
            sum += pj;
        }
        l = l * c + sum;
#pragma unroll
        for (int d = 0; d < HD; d++) oreg[d] *= c;
#pragma unroll
        for (int j = 0; j < KB; j++) {
            float pj = sarr[j];
#pragma unroll
            for (int dd = 0; dd < 16; dd++) {
                float4 v4 = *(const float4*)&Vs[j * KVPAD + 4 * dd];
                oreg[4 * dd + 0] += pj * v4.x;
                oreg[4 * dd + 1] += pj * v4.y;
                oreg[4 * dd + 2] += pj * v4.z;
                oreg[4 * dd + 3] += pj * v4.w;
            }
        }
        __syncthreads();   // PV reads done before next kblock overwrites xh/Ks/Vs
    }

    float inv = 1.0f / l;
#pragma unroll
    for (int d = 0; d < HD; d++) oreg[d] *= inv;

    // ---- Phase 3: project this head's slice and accumulate into out ----
    float* orow = out + (b * SEQ + q0 + tid) * CH;
    for (int j0 = 0; j0 < CH; j0 += 64) {
#pragma unroll
        for (int i = 0; i < 16; i++) {
            int e = tid + 256 * i;
            int d = e & 63, jj = e >> 6;
            ws[jj * 68 + d] = pw[(j0 + jj) * CH + h * HD + d];
        }
        __syncthreads();
#pragma unroll 4
        for (int jj = 0; jj < 64; jj++) {
            float acc = 0.f;
#pragma unroll
            for (int dd = 0; dd < 16; dd++) {
                float4 w4 = *(const float4*)&ws[jj * 68 + 4 * dd];
                acc += oreg[4 * dd + 0] * w4.x + oreg[4 * dd + 1] * w4.y
                     + oreg[4 * dd + 2] * w4.z + oreg[4 * dd + 3] * w4.w;
            }
            atomicAdd(orow + j0 + jj, acc);
        }
        __syncthreads();
    }
}

// ---------------------------------------------------------------------------

extern "C" void kernel_launch(void* const* d_in, const int* in_sizes, int n_in,
                              void* d_out, int out_size) {
    const float* x = 0; const float* qkv_w = 0;
    const float* proj_w = 0; const float* proj_b = 0;
    for (int i = 0; i < n_in; i++) {
        int s = in_sizes[i];
        const float* p = (const float*)d_in[i];
        if (s == NTOK * CH)        { if (!x) x = p; }
        else if (s == 3 * CH * CH) { if (!qkv_w) qkv_w = p; }
        else if (s == CH * CH)     { if (!proj_w) proj_w = p; }
        else if (s == CH)          { if (!proj_b) proj_b = p; }
    }
    if (!x || !qkv_w || !proj_w || !proj_b) {
        x      = (const float*)d_in[0];
        qkv_w  = (const float*)d_in[1];
        proj_w = (const float*)d_in[2];
        proj_b = (const float*)d_in[3];
    }
    float* out = (float*)d_out;

    static int smem_set = 0;
    if (!smem_set) {
        cudaFuncSetAttribute(fused_attn_kernel,
                             cudaFuncAttributeMaxDynamicSharedMemorySize, SMEM_TOTAL);
        smem_set = 1;
    }

    bias_init_kernel<<<(NTOK * CH + 255) / 256, 256>>>(proj_b, out, NTOK * CH);
    fused_attn_kernel<<<dim3(SEQ / QT, Bq * NH), 256, SMEM_TOTAL>>>(x, qkv_w, proj_w, out);
}

// round 8
// speedup vs baseline: 5.5844x; 1.7402x over previous
#include <cuda_runtime.h>
#include <cuda_fp16.h>
#include <cstdint>
#include <math.h>

#define Bq  4
#define SEQ 2048
#define CH  768
#define NH  12
#define HD  64
#define NTOK (Bq * SEQ)

#define QT  256     // q rows per CTA
#define KB  64      // keys per block

#define WPAD  776   // wh row stride in halves (768 + 8 -> 16B stagger)
#define XPAD  72    // half-buffer row stride (64 + 8 -> 16B stagger)
#define OPAD  68    // Osh row stride in floats

#define SZ_WH    (128 * WPAD * 2)            /* 198656 */
#define OFF_R    SZ_WH
#define SMEM_TOTAL (OFF_R + 20800)           /* 219456 bytes */

__global__ void bias_init_kernel(const float* __restrict__ bias,
                                 float* __restrict__ out, int n) {
    int i = blockIdx.x * blockDim.x + threadIdx.x;
    if (i < n) out[i] = bias[i % CH];
}

__device__ __forceinline__ void ldm_x4(unsigned int* r, const void* p) {
    unsigned int a = (unsigned int)__cvta_generic_to_shared(p);
    asm volatile("ldmatrix.sync.aligned.m8n8.x4.shared.b16 {%0,%1,%2,%3}, [%4];"
                 : "=r"(r[0]), "=r"(r[1]), "=r"(r[2]), "=r"(r[3]) : "r"(a));
}
__device__ __forceinline__ void ldm_x2(unsigned int* r, const void* p) {
    unsigned int a = (unsigned int)__cvta_generic_to_shared(p);
    asm volatile("ldmatrix.sync.aligned.m8n8.x2.shared.b16 {%0,%1}, [%2];"
                 : "=r"(r[0]), "=r"(r[1]) : "r"(a));
}
__device__ __forceinline__ void mma16816(float* c, const unsigned int* a,
                                         const unsigned int* b) {
    asm volatile("mma.sync.aligned.m16n8k16.row.col.f32.f16.f16.f32 "
                 "{%0,%1,%2,%3},{%4,%5,%6,%7},{%8,%9},{%0,%1,%2,%3};"
                 : "+f"(c[0]), "+f"(c[1]), "+f"(c[2]), "+f"(c[3])
                 : "r"(a[0]), "r"(a[1]), "r"(a[2]), "r"(a[3]), "r"(b[0]), "r"(b[1]));
}
__device__ __forceinline__ unsigned int pack_h2(float a, float b) {
    __half2 t = __floats2half2_rn(a, b);
    return *(unsigned int*)&t;
}

// CTA = (q-tile of 256 rows, one (b,h)). Full tensor-core FA2 pipeline:
// KV-proj, S, PV all on mma.m16n8k16; softmax in fragment registers.
__global__ __launch_bounds__(256) void fused_attn_kernel(
    const float* __restrict__ x,      // (4,2048,768)
    const float* __restrict__ w,      // qkv_w (2304,768)
    const float* __restrict__ pw,     // proj_w (768,768)
    float* __restrict__ out)          // (4,2048,768), pre-filled with bias
{
    extern __shared__ __align__(16) char smem[];
    half*  wh   = (half*)(smem);                  // [128][WPAD]: rows 0-63 wk, 64-127 wv
    half*  xh   = (half*)(smem + OFF_R);          // [KB][XPAD] staging (overlays Ksh)
    half*  Ksh  = (half*)(smem + OFF_R);          // [KB][XPAD] fp16
    half*  VshT = (half*)(smem + OFF_R + KB * XPAD * 2);  // [HD][XPAD] transposed V
    float* xq   = (float*)(smem + OFF_R);         // Q-phase overlay [16][257]
    float* wqs  = (float*)(smem + OFF_R + 16448); // [16][68]
    half*  qbuf = (half*)(smem + OFF_R);          // Q-bounce [4][32][XPAD]
    float* ws   = (float*)(smem + OFF_R);         // out-proj overlay [64][68]
    float* Osh  = (float*)(smem);                 // [256][OPAD] overlays wh (dead)

    int tid = threadIdx.x;
    int warp = tid >> 5, lane = tid & 31;
    int bh = blockIdx.y;
    int b = bh / NH, h = bh % NH;
    int q0 = blockIdx.x * QT;

    // ---- Stage K/V weights once: fp32 gmem -> fp16 smem ----
    for (int e = tid; e < 128 * 192; e += 256) {
        int n = e / 192, c4 = (e % 192) << 2;
        int grow = (n < 64) ? (CH + h * HD + n) : (2 * CH + h * HD + n - 64);
        float4 t = *(const float4*)&w[grow * CH + c4];
        half2* dst = (half2*)&wh[n * WPAD + c4];
        dst[0] = __floats2half2_rn(t.x, t.y);
        dst[1] = __floats2half2_rn(t.z, t.w);
    }

    // ---- Phase 1: scalar Q-proj (proven), row tid, scaled by hd^-0.5 ----
    float qreg[HD];
#pragma unroll
    for (int d = 0; d < HD; d++) qreg[d] = 0.f;

    for (int k0 = 0; k0 < CH; k0 += 16) {
        __syncthreads();   // also covers wh staging before later use
#pragma unroll
        for (int i = 0; i < 16; i++) {
            int e = tid + 256 * i;
            int r = e >> 4, kk = e & 15;
            xq[kk * 257 + r] = x[(b * SEQ + q0 + r) * CH + k0 + kk];
        }
#pragma unroll
        for (int i = 0; i < 4; i++) {
            int e = tid + 256 * i;
            int d = e >> 4, kk = e & 15;
            wqs[kk * 68 + d] = w[(h * HD + d) * CH + k0 + kk];
        }
        __syncthreads();
#pragma unroll
        for (int kk = 0; kk < 16; kk++) {
            float xv = xq[kk * 257 + tid];
#pragma unroll
            for (int dd = 0; dd < 16; dd++) {
                float4 w4 = *(const float4*)&wqs[kk * 68 + 4 * dd];
                qreg[4 * dd + 0] += xv * w4.x;
                qreg[4 * dd + 1] += xv * w4.y;
                qreg[4 * dd + 2] += xv * w4.z;
                qreg[4 * dd + 3] += xv * w4.w;
            }
        }
    }
#pragma unroll
    for (int d = 0; d < HD; d++) qreg[d] *= 0.125f;

    // ---- Convert Q rows -> persistent A-fragments (smem bounce, 2 passes) ----
    unsigned int qA[2][4][4];
#pragma unroll 1
    for (int pass = 0; pass < 2; pass++) {
        __syncthreads();
        if ((warp >> 2) == pass) {
            half* qb = qbuf + (warp & 3) * 32 * XPAD;
#pragma unroll
            for (int d = 0; d < HD; d += 2)
                *(half2*)&qb[lane * XPAD + d] = __floats2half2_rn(qreg[d], qreg[d + 1]);
        }
        __syncthreads();
        if ((warp >> 2) == pass) {
            half* qb = qbuf + (warp & 3) * 32 * XPAD;
#pragma unroll
            for (int mt = 0; mt < 2; mt++)
#pragma unroll
                for (int kt = 0; kt < 4; kt++)
                    ldm_x4(qA[mt][kt],
                           &qb[(mt * 16 + (lane & 15)) * XPAD + kt * 16 + ((lane >> 4) << 3)]);
        }
    }

    // ---- Main loop over 64-key blocks ----
    float mrow[4], lrow[4], ofr[2][8][4];
#pragma unroll
    for (int i = 0; i < 4; i++) { mrow[i] = -1e30f; lrow[i] = 0.f; }
#pragma unroll
    for (int mt = 0; mt < 2; mt++)
#pragma unroll
        for (int nt = 0; nt < 8; nt++)
#pragma unroll
            for (int q = 0; q < 4; q++) ofr[mt][nt][q] = 0.f;

    for (int kb = 0; kb < SEQ; kb += KB) {
        // --- K/V projection: M=64 keys, N=128 (64 K-dims | 64 V-dims), K=768 ---
        float cfr[4][2][4];
#pragma unroll
        for (int mt = 0; mt < 4; mt++)
#pragma unroll
            for (int nt = 0; nt < 2; nt++)
#pragma unroll
                for (int q = 0; q < 4; q++) cfr[mt][nt][q] = 0.f;

        for (int ch = 0; ch < 12; ch++) {
            __syncthreads();   // prior Ksh/VshT reads (or xh ldmatrix) complete
#pragma unroll
            for (int i = 0; i < 4; i++) {
                int e = tid + 256 * i;
                int row = e >> 4, cg = (e & 15) << 2;
                float4 t = *(const float4*)&x[(b * SEQ + kb + row) * CH + ch * 64 + cg];
                half2* dst = (half2*)&xh[row * XPAD + cg];
                dst[0] = __floats2half2_rn(t.x, t.y);
                dst[1] = __floats2half2_rn(t.z, t.w);
            }
            __syncthreads();
#pragma unroll
            for (int kt = 0; kt < 4; kt++) {
                unsigned int afr[4][4], bfr[2][2];
#pragma unroll
                for (int mt = 0; mt < 4; mt++)
                    ldm_x4(afr[mt],
                           &xh[(mt * 16 + (lane & 15)) * XPAD + kt * 16 + ((lane >> 4) << 3)]);
#pragma unroll
                for (int nt = 0; nt < 2; nt++) {
                    int l16 = lane & 15;
                    int row = warp * 16 + nt * 8 + (l16 & 7);
                    int kcol = ch * 64 + kt * 16 + ((l16 >> 3) << 3);
                    ldm_x2(bfr[nt], &wh[row * WPAD + kcol]);
                }
#pragma unroll
                for (int mt = 0; mt < 4; mt++)
#pragma unroll
                    for (int nt = 0; nt < 2; nt++)
                        mma16816(cfr[mt][nt], afr[mt], bfr[nt]);
            }
        }
        __syncthreads();   // xh consumed before Ksh/VshT overwrite

        // --- Epilogue: K warps (0-3) -> Ksh[key][dim]; V warps (4-7) -> VshT[dim][key]
        if (warp < 4) {
            int d0 = warp * 16;
#pragma unroll
            for (int mt = 0; mt < 4; mt++)
#pragma unroll
                for (int nt = 0; nt < 2; nt++) {
                    int key = mt * 16 + (lane >> 2);
                    int dim = d0 + nt * 8 + ((lane & 3) << 1);
                    *(half2*)&Ksh[key * XPAD + dim] = __floats2half2_rn(cfr[mt][nt][0], cfr[mt][nt][1]);
                    *(half2*)&Ksh[(key + 8) * XPAD + dim] = __floats2half2_rn(cfr[mt][nt][2], cfr[mt][nt][3]);
                }
        } else {
            int d0 = (warp - 4) * 16;
#pragma unroll
            for (int mt = 0; mt < 4; mt++)
#pragma unroll
                for (int nt = 0; nt < 2; nt++) {
                    int key = mt * 16 + (lane >> 2);
                    int dim = d0 + nt * 8 + ((lane & 3) << 1);
                    VshT[dim * XPAD + key]           = __float2half(cfr[mt][nt][0]);
                    VshT[(dim + 1) * XPAD + key]     = __float2half(cfr[mt][nt][1]);
                    VshT[dim * XPAD + key + 8]       = __float2half(cfr[mt][nt][2]);
                    VshT[(dim + 1) * XPAD + key + 8] = __float2half(cfr[mt][nt][3]);
                }
        }
        __syncthreads();

        // --- S = Q @ K^T (64 q-rows per... 32 q-rows per warp x 64 keys) ---
        float sfr[2][8][4];
#pragma unroll
        for (int mt = 0; mt < 2; mt++)
#pragma unroll
            for (int nt = 0; nt < 8; nt++)
#pragma unroll
                for (int q = 0; q < 4; q++) sfr[mt][nt][q] = 0.f;

        int g = lane >> 3;
#pragma unroll
        for (int kt = 0; kt < 4; kt++) {
            unsigned int bfr[8][2];
#pragma unroll
            for (int np = 0; np < 4; np++) {
                unsigned int r4[4];
                ldm_x4(r4, &Ksh[(np * 16 + (g & 1) * 8 + (lane & 7)) * XPAD
                                + kt * 16 + ((g >> 1) << 3)]);
                bfr[2 * np][0] = r4[0];     bfr[2 * np][1] = r4[2];
                bfr[2 * np + 1][0] = r4[1]; bfr[2 * np + 1][1] = r4[3];
            }
#pragma unroll
            for (int mt = 0; mt < 2; mt++)
#pragma unroll
                for (int nt = 0; nt < 8; nt++)
                    mma16816(sfr[mt][nt], qA[mt][kt], bfr[nt]);
        }

        // --- Online softmax in fragments (4 rows per lane, quad shuffles) ---
#pragma unroll
        for (int mt = 0; mt < 2; mt++)
#pragma unroll
            for (int hf = 0; hf < 2; hf++) {
                int ri = mt * 2 + hf;
                float mx = mrow[ri];
#pragma unroll
                for (int nt = 0; nt < 8; nt++)
                    mx = fmaxf(mx, fmaxf(sfr[mt][nt][hf * 2], sfr[mt][nt][hf * 2 + 1]));
                mx = fmaxf(mx, __shfl_xor_sync(0xffffffffu, mx, 1));
                mx = fmaxf(mx, __shfl_xor_sync(0xffffffffu, mx, 2));
                float c = __expf(mrow[ri] - mx);
                mrow[ri] = mx;
                float sum = 0.f;
#pragma unroll
                for (int nt = 0; nt < 8; nt++) {
                    float p0 = __expf(sfr[mt][nt][hf * 2] - mx);
                    float p1 = __expf(sfr[mt][nt][hf * 2 + 1] - mx);
                    sfr[mt][nt][hf * 2] = p0; sfr[mt][nt][hf * 2 + 1] = p1;
                    sum += p0 + p1;
                }
                sum += __shfl_xor_sync(0xffffffffu, sum, 1);
                sum += __shfl_xor_sync(0xffffffffu, sum, 2);
                lrow[ri] = lrow[ri] * c + sum;
#pragma unroll
                for (int nt = 0; nt < 8; nt++) {
                    ofr[mt][nt][hf * 2] *= c;
                    ofr[mt][nt][hf * 2 + 1] *= c;
                }
            }

        // --- P (fp16 A-frags) from S C-frags ---
        unsigned int pA[2][4][4];
#pragma unroll
        for (int mt = 0; mt < 2; mt++)
#pragma unroll
            for (int kt = 0; kt < 4; kt++) {
                pA[mt][kt][0] = pack_h2(sfr[mt][2 * kt][0], sfr[mt][2 * kt][1]);
                pA[mt][kt][1] = pack_h2(sfr[mt][2 * kt][2], sfr[mt][2 * kt][3]);
                pA[mt][kt][2] = pack_h2(sfr[mt][2 * kt + 1][0], sfr[mt][2 * kt + 1][1]);
                pA[mt][kt][3] = pack_h2(sfr[mt][2 * kt + 1][2], sfr[mt][2 * kt + 1][3]);
            }

        // --- O += P @ V (B-frags from VshT, non-trans ldmatrix) ---
#pragma unroll
        for (int kt = 0; kt < 4; kt++) {
            unsigned int bfr[8][2];
#pragma unroll
            for (int np = 0; np < 4; np++) {
                unsigned int r4[4];
                ldm_x4(r4, &VshT[(np * 16 + (g & 1) * 8 + (lane & 7)) * XPAD
                                 + kt * 16 + ((g >> 1) << 3)]);
                bfr[2 * np][0] = r4[0];     bfr[2 * np][1] = r4[2];
                bfr[2 * np + 1][0] = r4[1]; bfr[2 * np + 1][1] = r4[3];
            }
#pragma unroll
            for (int mt = 0; mt < 2; mt++)
#pragma unroll
                for (int nt = 0; nt < 8; nt++)
                    mma16816(ofr[mt][nt], pA[mt][kt], bfr[nt]);
        }
    }

    // ---- O fragments -> Osh (overlaying dead weight region), /l ----
    float inv[4];
#pragma unroll
    for (int i = 0; i < 4; i++) inv[i] = 1.0f / lrow[i];
#pragma unroll
    for (int mt = 0; mt < 2; mt++)
#pragma unroll
        for (int nt = 0; nt < 8; nt++) {
            int r = 32 * warp + mt * 16 + (lane >> 2);
            int c = nt * 8 + ((lane & 3) << 1);
            *(float2*)&Osh[r * OPAD + c] =
                make_float2(ofr[mt][nt][0] * inv[mt * 2], ofr[mt][nt][1] * inv[mt * 2]);
            *(float2*)&Osh[(r + 8) * OPAD + c] =
                make_float2(ofr[mt][nt][2] * inv[mt * 2 + 1], ofr[mt][nt][3] * inv[mt * 2 + 1]);
        }
    __syncthreads();

    float oreg[HD];
#pragma unroll
    for (int dd = 0; dd < 16; dd++) {
        float4 t = *(const float4*)&Osh[tid * OPAD + 4 * dd];
        oreg[4 * dd + 0] = t.x; oreg[4 * dd + 1] = t.y;
        oreg[4 * dd + 2] = t.z; oreg[4 * dd + 3] = t.w;
    }
    __syncthreads();

    // ---- Phase 3 (proven): project head slice, accumulate into out ----
    float* orow = out + (b * SEQ + q0 + tid) * CH;
    for (int j0 = 0; j0 < CH; j0 += 64) {
#pragma unroll
        for (int i = 0; i < 16; i++) {
            int e = tid + 256 * i;
            int d = e & 63, jj = e >> 6;
            ws[jj * 68 + d] = pw[(j0 + jj) * CH + h * HD + d];
        }
        __syncthreads();
#pragma unroll 4
        for (int jj = 0; jj < 64; jj++) {
            float acc = 0.f;
#pragma unroll
            for (int dd = 0; dd < 16; dd++) {
                float4 w4 = *(const float4*)&ws[jj * 68 + 4 * dd];
                acc += oreg[4 * dd + 0] * w4.x + oreg[4 * dd + 1] * w4.y
                     + oreg[4 * dd + 2] * w4.z + oreg[4 * dd + 3] * w4.w;
            }
            atomicAdd(orow + j0 + jj, acc);
        }
        __syncthreads();
    }
}

// ---------------------------------------------------------------------------

extern "C" void kernel_launch(void* const* d_in, const int* in_sizes, int n_in,
                              void* d_out, int out_size) {
    const float* x = 0; const float* qkv_w = 0;
    const float* proj_w = 0; const float* proj_b = 0;
    for (int i = 0; i < n_in; i++) {
        int s = in_sizes[i];
        const float* p = (const float*)d_in[i];
        if (s == NTOK * CH)        { if (!x) x = p; }
        else if (s == 3 * CH * CH) { if (!qkv_w) qkv_w = p; }
        else if (s == CH * CH)     { if (!proj_w) proj_w = p; }
        else if (s == CH)          { if (!proj_b) proj_b = p; }
    }
    if (!x || !qkv_w || !proj_w || !proj_b) {
        x      = (const float*)d_in[0];
        qkv_w  = (const float*)d_in[1];
        proj_w = (const float*)d_in[2];
        proj_b = (const float*)d_in[3];
    }
    float* out = (float*)d_out;

    static int smem_set = 0;
    if (!smem_set) {
        cudaFuncSetAttribute(fused_attn_kernel,
                             cudaFuncAttributeMaxDynamicSharedMemorySize, SMEM_TOTAL);
        smem_set = 1;
    }

    bias_init_kernel<<<(NTOK * CH + 255) / 256, 256>>>(proj_b, out, NTOK * CH);
    fused_attn_kernel<<<dim3(SEQ / QT, Bq * NH), 256, SMEM_TOTAL>>>(x, qkv_w, proj_w, out);
}

// round 9
// speedup vs baseline: 5.7868x; 1.0362x over previous
#include <cuda_runtime.h>
#include <cuda_fp16.h>
#include <cstdint>
#include <math.h>

#define Bq  4
#define SEQ 2048
#define CH  768
#define NH  12
#define HD  64
#define NTOK (Bq * SEQ)

#define QT  256     // q rows per CTA
#define KB  64      // keys per block

#define WPAD  776   // wh row stride in halves
#define XPAD  72    // Ksh/VshT/qbuf row stride in halves
#define XHP   56    // xh staging row stride in halves (48 + 8)
#define OPAD  68    // Osh row stride in floats

#define SZ_WH    (128 * WPAD * 2)            /* 198656 */
#define OFF_R    SZ_WH
#define OFF_XH0  (OFF_R)
#define OFF_XH1  (OFF_R + 64 * XHP * 2)      /* +7168  */
#define OFF_KS   (OFF_R + 2 * 64 * XHP * 2)  /* +14336 */
#define OFF_VS   (OFF_KS + 64 * XPAD * 2)    /* +23552 */
#define SMEM_TOTAL (OFF_VS + 64 * XPAD * 2)  /* 231424 bytes */

__global__ void bias_init_kernel(const float* __restrict__ bias,
                                 float* __restrict__ out, int n) {
    int i = blockIdx.x * blockDim.x + threadIdx.x;
    if (i < n) out[i] = bias[i % CH];
}

__device__ __forceinline__ void ldm_x4(unsigned int* r, const void* p) {
    unsigned int a = (unsigned int)__cvta_generic_to_shared(p);
    asm volatile("ldmatrix.sync.aligned.m8n8.x4.shared.b16 {%0,%1,%2,%3}, [%4];"
                 : "=r"(r[0]), "=r"(r[1]), "=r"(r[2]), "=r"(r[3]) : "r"(a));
}
__device__ __forceinline__ void ldm_x2(unsigned int* r, const void* p) {
    unsigned int a = (unsigned int)__cvta_generic_to_shared(p);
    asm volatile("ldmatrix.sync.aligned.m8n8.x2.shared.b16 {%0,%1}, [%2];"
                 : "=r"(r[0]), "=r"(r[1]) : "r"(a));
}
__device__ __forceinline__ void mma16816(float* c, const unsigned int* a,
                                         const unsigned int* b) {
    asm volatile("mma.sync.aligned.m16n8k16.row.col.f32.f16.f16.f32 "
                 "{%0,%1,%2,%3},{%4,%5,%6,%7},{%8,%9},{%0,%1,%2,%3};"
                 : "+f"(c[0]), "+f"(c[1]), "+f"(c[2]), "+f"(c[3])
                 : "r"(a[0]), "r"(a[1]), "r"(a[2]), "r"(a[3]), "r"(b[0]), "r"(b[1]));
}
__device__ __forceinline__ unsigned int pack_h2(float a, float b) {
    __half2 t = __floats2half2_rn(a, b);
    return *(unsigned int*)&t;
}

// CTA = (q-tile of 256 rows, one (b,h)). Tensor-core FA2 pipeline with
// software-pipelined (double-buffered) x staging for the KV projection.
__global__ __launch_bounds__(256) void fused_attn_kernel(
    const float* __restrict__ x,      // (4,2048,768)
    const float* __restrict__ w,      // qkv_w (2304,768)
    const float* __restrict__ pw,     // proj_w (768,768)
    float* __restrict__ out)          // (4,2048,768), pre-filled with bias
{
    extern __shared__ __align__(16) char smem[];
    half*  wh   = (half*)(smem);                  // [128][WPAD]: rows 0-63 wk, 64-127 wv
    half*  xh0  = (half*)(smem + OFF_XH0);        // [64][XHP] staging buf 0
    half*  xh1  = (half*)(smem + OFF_XH1);        // [64][XHP] staging buf 1
    half*  Ksh  = (half*)(smem + OFF_KS);         // [64][XPAD]
    half*  VshT = (half*)(smem + OFF_VS);         // [64][XPAD] transposed V
    float* xq   = (float*)(smem + OFF_R);         // Q-phase overlay [16][257]
    float* wqs  = (float*)(smem + OFF_R + 16448); // [16][68]
    half*  qbuf = (half*)(smem + OFF_R);          // Q-bounce [4][32][XPAD]
    float* ws   = (float*)(smem + OFF_R);         // out-proj overlay [64][68]
    float* Osh  = (float*)(smem);                 // [256][OPAD] overlays wh (dead)

    int tid = threadIdx.x;
    int warp = tid >> 5, lane = tid & 31;
    int bh = blockIdx.y;
    int b = bh / NH, h = bh % NH;
    int q0 = blockIdx.x * QT;

    // ---- Stage K/V weights once: fp32 gmem -> fp16 smem ----
    for (int e = tid; e < 128 * 192; e += 256) {
        int n = e / 192, c4 = (e % 192) << 2;
        int grow = (n < 64) ? (CH + h * HD + n) : (2 * CH + h * HD + n - 64);
        float4 t = *(const float4*)&w[grow * CH + c4];
        half2* dst = (half2*)&wh[n * WPAD + c4];
        dst[0] = __floats2half2_rn(t.x, t.y);
        dst[1] = __floats2half2_rn(t.z, t.w);
    }

    // ---- Phase 1: scalar Q-proj (proven), row tid, scaled by hd^-0.5 ----
    float qreg[HD];
#pragma unroll
    for (int d = 0; d < HD; d++) qreg[d] = 0.f;

    for (int k0 = 0; k0 < CH; k0 += 16) {
        __syncthreads();
#pragma unroll
        for (int i = 0; i < 16; i++) {
            int e = tid + 256 * i;
            int r = e >> 4, kk = e & 15;
            xq[kk * 257 + r] = x[(b * SEQ + q0 + r) * CH + k0 + kk];
        }
#pragma unroll
        for (int i = 0; i < 4; i++) {
            int e = tid + 256 * i;
            int d = e >> 4, kk = e & 15;
            wqs[kk * 68 + d] = w[(h * HD + d) * CH + k0 + kk];
        }
        __syncthreads();
#pragma unroll
        for (int kk = 0; kk < 16; kk++) {
            float xv = xq[kk * 257 + tid];
#pragma unroll
            for (int dd = 0; dd < 16; dd++) {
                float4 w4 = *(const float4*)&wqs[kk * 68 + 4 * dd];
                qreg[4 * dd + 0] += xv * w4.x;
                qreg[4 * dd + 1] += xv * w4.y;
                qreg[4 * dd + 2] += xv * w4.z;
                qreg[4 * dd + 3] += xv * w4.w;
            }
        }
    }
#pragma unroll
    for (int d = 0; d < HD; d++) qreg[d] *= 0.125f;

    // ---- Convert Q rows -> persistent A-fragments (smem bounce, 2 passes) ----
    unsigned int qA[2][4][4];
#pragma unroll 1
    for (int pass = 0; pass < 2; pass++) {
        __syncthreads();
        if ((warp >> 2) == pass) {
            half* qb = qbuf + (warp & 3) * 32 * XPAD;
#pragma unroll
            for (int d = 0; d < HD; d += 2)
                *(half2*)&qb[lane * XPAD + d] = __floats2half2_rn(qreg[d], qreg[d + 1]);
        }
        __syncthreads();
        if ((warp >> 2) == pass) {
            half* qb = qbuf + (warp & 3) * 32 * XPAD;
#pragma unroll
            for (int mt = 0; mt < 2; mt++)
#pragma unroll
                for (int kt = 0; kt < 4; kt++)
                    ldm_x4(qA[mt][kt],
                           &qb[(mt * 16 + (lane & 15)) * XPAD + kt * 16 + ((lane >> 4) << 3)]);
        }
    }
    __syncthreads();   // qbuf reads done before xh0 staging overlays it

    // ---- Main loop over 64-key blocks ----
    float mrow[4], lrow[4], ofr[2][8][4];
#pragma unroll
    for (int i = 0; i < 4; i++) { mrow[i] = -1e30f; lrow[i] = 0.f; }
#pragma unroll
    for (int mt = 0; mt < 2; mt++)
#pragma unroll
        for (int nt = 0; nt < 8; nt++)
#pragma unroll
            for (int q = 0; q < 4; q++) ofr[mt][nt][q] = 0.f;

    // Prefetch chunk 0 of kblock 0
    float4 pre[3];
#pragma unroll
    for (int i = 0; i < 3; i++) {
        int e = tid + 256 * i;
        int r = e / 12, c4 = (e % 12) << 2;
        pre[i] = *(const float4*)&x[(b * SEQ + 0 + r) * CH + 0 + c4];
    }

    for (int kb = 0; kb < SEQ; kb += KB) {
        // Store prefetched chunk 0 into xh0 (visible after ch=0's sync)
#pragma unroll
        for (int i = 0; i < 3; i++) {
            int e = tid + 256 * i;
            int r = e / 12, c4 = (e % 12) << 2;
            half2* dst = (half2*)&xh0[r * XHP + c4];
            dst[0] = __floats2half2_rn(pre[i].x, pre[i].y);
            dst[1] = __floats2half2_rn(pre[i].z, pre[i].w);
        }

        float cfr[4][2][4];
#pragma unroll
        for (int mt = 0; mt < 4; mt++)
#pragma unroll
            for (int nt = 0; nt < 2; nt++)
#pragma unroll
                for (int q = 0; q < 4; q++) cfr[mt][nt][q] = 0.f;

        // 16 chunks of 48 k-dims, software-pipelined: prefetch ch+1 during mma(ch)
#pragma unroll 1
        for (int ch = 0; ch < 16; ch++) {
            __syncthreads();   // staged buffer visible; prev buffer reads done
            if (ch < 15) {
#pragma unroll
                for (int i = 0; i < 3; i++) {
                    int e = tid + 256 * i;
                    int r = e / 12, c4 = (e % 12) << 2;
                    pre[i] = *(const float4*)&x[(b * SEQ + kb + r) * CH + (ch + 1) * 48 + c4];
                }
            }
            half* cur = (ch & 1) ? xh1 : xh0;
#pragma unroll
            for (int kt = 0; kt < 3; kt++) {
                unsigned int afr[4][4], bfr[2][2];
#pragma unroll
                for (int mt = 0; mt < 4; mt++)
                    ldm_x4(afr[mt],
                           &cur[(mt * 16 + (lane & 15)) * XHP + kt * 16 + ((lane >> 4) << 3)]);
#pragma unroll
                for (int nt = 0; nt < 2; nt++) {
                    int l16 = lane & 15;
                    int row = warp * 16 + nt * 8 + (l16 & 7);
                    int kcol = ch * 48 + kt * 16 + ((l16 >> 3) << 3);
                    ldm_x2(bfr[nt], &wh[row * WPAD + kcol]);
                }
#pragma unroll
                for (int mt = 0; mt < 4; mt++)
#pragma unroll
                    for (int nt = 0; nt < 2; nt++)
                        mma16816(cfr[mt][nt], afr[mt], bfr[nt]);
            }
            if (ch < 15) {
                half* nxt = (ch & 1) ? xh0 : xh1;
#pragma unroll
                for (int i = 0; i < 3; i++) {
                    int e = tid + 256 * i;
                    int r = e / 12, c4 = (e % 12) << 2;
                    half2* dst = (half2*)&nxt[r * XHP + c4];
                    dst[0] = __floats2half2_rn(pre[i].x, pre[i].y);
                    dst[1] = __floats2half2_rn(pre[i].z, pre[i].w);
                }
            }
        }

        // Prefetch chunk 0 of the NEXT kblock (covered by epilogue/S/softmax/PV)
        {
            int nkb = (kb + KB < SEQ) ? kb + KB : kb;
#pragma unroll
            for (int i = 0; i < 3; i++) {
                int e = tid + 256 * i;
                int r = e / 12, c4 = (e % 12) << 2;
                pre[i] = *(const float4*)&x[(b * SEQ + nkb + r) * CH + 0 + c4];
            }
        }

        // --- Epilogue: K warps (0-3) -> Ksh[key][dim]; V warps (4-7) -> VshT[dim][key]
        if (warp < 4) {
            int d0 = warp * 16;
#pragma unroll
            for (int mt = 0; mt < 4; mt++)
#pragma unroll
                for (int nt = 0; nt < 2; nt++) {
                    int key = mt * 16 + (lane >> 2);
                    int dim = d0 + nt * 8 + ((lane & 3) << 1);
                    *(half2*)&Ksh[key * XPAD + dim] = __floats2half2_rn(cfr[mt][nt][0], cfr[mt][nt][1]);
                    *(half2*)&Ksh[(key + 8) * XPAD + dim] = __floats2half2_rn(cfr[mt][nt][2], cfr[mt][nt][3]);
                }
        } else {
            int d0 = (warp - 4) * 16;
#pragma unroll
            for (int mt = 0; mt < 4; mt++)
#pragma unroll
                for (int nt = 0; nt < 2; nt++) {
                    int key = mt * 16 + (lane >> 2);
                    int dim = d0 + nt * 8 + ((lane & 3) << 1);
                    VshT[dim * XPAD + key]           = __float2half(cfr[mt][nt][0]);
                    VshT[(dim + 1) * XPAD + key]     = __float2half(cfr[mt][nt][1]);
                    VshT[dim * XPAD + key + 8]       = __float2half(cfr[mt][nt][2]);
                    VshT[(dim + 1) * XPAD + key + 8] = __float2half(cfr[mt][nt][3]);
                }
        }
        __syncthreads();

        // --- S = Q @ K^T (32 q-rows per warp x 64 keys) ---
        float sfr[2][8][4];
#pragma unroll
        for (int mt = 0; mt < 2; mt++)
#pragma unroll
            for (int nt = 0; nt < 8; nt++)
#pragma unroll
                for (int q = 0; q < 4; q++) sfr[mt][nt][q] = 0.f;

        int g = lane >> 3;
#pragma unroll
        for (int kt = 0; kt < 4; kt++) {
            unsigned int bfr[8][2];
#pragma unroll
            for (int np = 0; np < 4; np++) {
                unsigned int r4[4];
                ldm_x4(r4, &Ksh[(np * 16 + (g & 1) * 8 + (lane & 7)) * XPAD
                                + kt * 16 + ((g >> 1) << 3)]);
                bfr[2 * np][0] = r4[0];     bfr[2 * np][1] = r4[2];
                bfr[2 * np + 1][0] = r4[1]; bfr[2 * np + 1][1] = r4[3];
            }
#pragma unroll
            for (int mt = 0; mt < 2; mt++)
#pragma unroll
                for (int nt = 0; nt < 8; nt++)
                    mma16816(sfr[mt][nt], qA[mt][kt], bfr[nt]);
        }

        // --- Online softmax in fragments (4 rows per lane, quad shuffles) ---
#pragma unroll
        for (int mt = 0; mt < 2; mt++)
#pragma unroll
            for (int hf = 0; hf < 2; hf++) {
                int ri = mt * 2 + hf;
                float mx = mrow[ri];
#pragma unroll
                for (int nt = 0; nt < 8; nt++)
                    mx = fmaxf(mx, fmaxf(sfr[mt][nt][hf * 2], sfr[mt][nt][hf * 2 + 1]));
                mx = fmaxf(mx, __shfl_xor_sync(0xffffffffu, mx, 1));
                mx = fmaxf(mx, __shfl_xor_sync(0xffffffffu, mx, 2));
                float c = __expf(mrow[ri] - mx);
                mrow[ri] = mx;
                float sum = 0.f;
#pragma unroll
                for (int nt = 0; nt < 8; nt++) {
                    float p0 = __expf(sfr[mt][nt][hf * 2] - mx);
                    float p1 = __expf(sfr[mt][nt][hf * 2 + 1] - mx);
                    sfr[mt][nt][hf * 2] = p0; sfr[mt][nt][hf * 2 + 1] = p1;
                    sum += p0 + p1;
                }
                sum += __shfl_xor_sync(0xffffffffu, sum, 1);
                sum += __shfl_xor_sync(0xffffffffu, sum, 2);
                lrow[ri] = lrow[ri] * c + sum;
#pragma unroll
                for (int nt = 0; nt < 8; nt++) {
                    ofr[mt][nt][hf * 2] *= c;
                    ofr[mt][nt][hf * 2 + 1] *= c;
                }
            }

        // --- P (fp16 A-frags) from S C-frags ---
        unsigned int pA[2][4][4];
#pragma unroll
        for (int mt = 0; mt < 2; mt++)
#pragma unroll
            for (int kt = 0; kt < 4; kt++) {
                pA[mt][kt][0] = pack_h2(sfr[mt][2 * kt][0], sfr[mt][2 * kt][1]);
                pA[mt][kt][1] = pack_h2(sfr[mt][2 * kt][2], sfr[mt][2 * kt][3]);
                pA[mt][kt][2] = pack_h2(sfr[mt][2 * kt + 1][0], sfr[mt][2 * kt + 1][1]);
                pA[mt][kt][3] = pack_h2(sfr[mt][2 * kt + 1][2], sfr[mt][2 * kt + 1][3]);
            }

        // --- O += P @ V (B-frags from VshT, non-trans ldmatrix) ---
#pragma unroll
        for (int kt = 0; kt < 4; kt++) {
            unsigned int bfr[8][2];
#pragma unroll
            for (int np = 0; np < 4; np++) {
                unsigned int r4[4];
                ldm_x4(r4, &VshT[(np * 16 + (g & 1) * 8 + (lane & 7)) * XPAD
                                 + kt * 16 + ((g >> 1) << 3)]);
                bfr[2 * np][0] = r4[0];     bfr[2 * np][1] = r4[2];
                bfr[2 * np + 1][0] = r4[1]; bfr[2 * np + 1][1] = r4[3];
            }
#pragma unroll
            for (int mt = 0; mt < 2; mt++)
#pragma unroll
                for (int nt = 0; nt < 8; nt++)
                    mma16816(ofr[mt][nt], pA[mt][kt], bfr[nt]);
        }
    }

    // ---- O fragments -> Osh (overlaying dead weight region), /l ----
    float inv[4];
#pragma unroll
    for (int i = 0; i < 4; i++) inv[i] = 1.0f / lrow[i];
#pragma unroll
    for (int mt = 0; mt < 2; mt++)
#pragma unroll
        for (int nt = 0; nt < 8; nt++) {
            int r = 32 * warp + mt * 16 + (lane >> 2);
            int c = nt * 8 + ((lane & 3) << 1);
            *(float2*)&Osh[r * OPAD + c] =
                make_float2(ofr[mt][nt][0] * inv[mt * 2], ofr[mt][nt][1] * inv[mt * 2]);
            *(float2*)&Osh[(r + 8) * OPAD + c] =
                make_float2(ofr[mt][nt][2] * inv[mt * 2 + 1], ofr[mt][nt][3] * inv[mt * 2 + 1]);
        }
    __syncthreads();

    float oreg[HD];
#pragma unroll
    for (int dd = 0; dd < 16; dd++) {
        float4 t = *(const float4*)&Osh[tid * OPAD + 4 * dd];
        oreg[4 * dd + 0] = t.x; oreg[4 * dd + 1] = t.y;
        oreg[4 * dd + 2] = t.z; oreg[4 * dd + 3] = t.w;
    }
    __syncthreads();

    // ---- Phase 3 (proven): project head slice, accumulate into out ----
    float* orow = out + (b * SEQ + q0 + tid) * CH;
    for (int j0 = 0; j0 < CH; j0 += 64) {
#pragma unroll
        for (int i = 0; i < 16; i++) {
            int e = tid + 256 * i;
            int d = e & 63, jj = e >> 6;
            ws[jj * 68 + d] = pw[(j0 + jj) * CH + h * HD + d];
        }
        __syncthreads();
#pragma unroll 4
        for (int jj = 0; jj < 64; jj++) {
            float acc = 0.f;
#pragma unroll
            for (int dd = 0; dd < 16; dd++) {
                float4 w4 = *(const float4*)&ws[jj * 68 + 4 * dd];
                acc += oreg[4 * dd + 0] * w4.x + oreg[4 * dd + 1] * w4.y
                     + oreg[4 * dd + 2] * w4.z + oreg[4 * dd + 3] * w4.w;
            }
            atomicAdd(orow + j0 + jj, acc);
        }
        __syncthreads();
    }
}

// ---------------------------------------------------------------------------

extern "C" void kernel_launch(void* const* d_in, const int* in_sizes, int n_in,
                              void* d_out, int out_size) {
    const float* x = 0; const float* qkv_w = 0;
    const float* proj_w = 0; const float* proj_b = 0;
    for (int i = 0; i < n_in; i++) {
        int s = in_sizes[i];
        const float* p = (const float*)d_in[i];
        if (s == NTOK * CH)        { if (!x) x = p; }
        else if (s == 3 * CH * CH) { if (!qkv_w) qkv_w = p; }
        else if (s == CH * CH)     { if (!proj_w) proj_w = p; }
        else if (s == CH)          { if (!proj_b) proj_b = p; }
    }
    if (!x || !qkv_w || !proj_w || !proj_b) {
        x      = (const float*)d_in[0];
        qkv_w  = (const float*)d_in[1];
        proj_w = (const float*)d_in[2];
        proj_b = (const float*)d_in[3];
    }
    float* out = (float*)d_out;

    static int smem_set = 0;
    if (!smem_set) {
        cudaFuncSetAttribute(fused_attn_kernel,
                             cudaFuncAttributeMaxDynamicSharedMemorySize, SMEM_TOTAL);
        smem_set = 1;
    }

    bias_init_kernel<<<(NTOK * CH + 255) / 256, 256>>>(proj_b, out, NTOK * CH);
    fused_attn_kernel<<<dim3(SEQ / QT, Bq * NH), 256, SMEM_TOTAL>>>(x, qkv_w, proj_w, out);
}

// round 10
// speedup vs baseline: 5.7895x; 1.0005x over previous
#include <cuda_runtime.h>
#include <cuda_fp16.h>
#include <cstdint>
#include <math.h>

#define Bq  4
#define SEQ 2048
#define CH  768
#define NH  12
#define HD  64
#define NTOK (Bq * SEQ)

#define QT  256     // q rows per CTA
#define KB  64      // keys per block

#define WPAD  776   // wh row stride in halves
#define XPAD  72    // Ksh/VshT/qbuf row stride in halves
#define XHP   56    // xh staging row stride in halves (48 + 8)
#define OPAD  68    // Osh row stride in floats

#define SZ_WH    (128 * WPAD * 2)            /* 198656 */
#define OFF_R    SZ_WH
#define OFF_XH0  (OFF_R)
#define OFF_XH1  (OFF_R + 64 * XHP * 2)      /* +7168  */
#define OFF_KS   (OFF_R + 2 * 64 * XHP * 2)  /* +14336 */
#define OFF_VS   (OFF_KS + 64 * XPAD * 2)    /* +23552 */
#define SMEM_TOTAL (OFF_VS + 64 * XPAD * 2)  /* 231424 bytes */

__global__ void bias_init_kernel(const float* __restrict__ bias,
                                 float* __restrict__ out, int n) {
    int i = blockIdx.x * blockDim.x + threadIdx.x;
    if (i < n) out[i] = bias[i % CH];
}

__device__ __forceinline__ void ldm_x4(unsigned int* r, const void* p) {
    unsigned int a = (unsigned int)__cvta_generic_to_shared(p);
    asm volatile("ldmatrix.sync.aligned.m8n8.x4.shared.b16 {%0,%1,%2,%3}, [%4];"
                 : "=r"(r[0]), "=r"(r[1]), "=r"(r[2]), "=r"(r[3]) : "r"(a));
}
__device__ __forceinline__ void ldm_x2(unsigned int* r, const void* p) {
    unsigned int a = (unsigned int)__cvta_generic_to_shared(p);
    asm volatile("ldmatrix.sync.aligned.m8n8.x2.shared.b16 {%0,%1}, [%2];"
                 : "=r"(r[0]), "=r"(r[1]) : "r"(a));
}
__device__ __forceinline__ void mma16816(float* c, const unsigned int* a,
                                         const unsigned int* b) {
    asm volatile("mma.sync.aligned.m16n8k16.row.col.f32.f16.f16.f32 "
                 "{%0,%1,%2,%3},{%4,%5,%6,%7},{%8,%9},{%0,%1,%2,%3};"
                 : "+f"(c[0]), "+f"(c[1]), "+f"(c[2]), "+f"(c[3])
                 : "r"(a[0]), "r"(a[1]), "r"(a[2]), "r"(a[3]), "r"(b[0]), "r"(b[1]));
}
__device__ __forceinline__ unsigned int pack_h2(float a, float b) {
    __half2 t = __floats2half2_rn(a, b);
    return *(unsigned int*)&t;
}

// CTA = (q-tile of 256 rows, one (b,h)). Tensor-core FA2 pipeline with
// software-pipelined (double-buffered) x staging for the KV projection.
__global__ __launch_bounds__(256) void fused_attn_kernel(
    const float* __restrict__ x,      // (4,2048,768)
    const float* __restrict__ w,      // qkv_w (2304,768)
    const float* __restrict__ pw,     // proj_w (768,768)
    float* __restrict__ out)          // (4,2048,768), pre-filled with bias
{
    extern __shared__ __align__(16) char smem[];
    half*  wh   = (half*)(smem);                  // [128][WPAD]: rows 0-63 wk, 64-127 wv
    half*  xh0  = (half*)(smem + OFF_XH0);        // [64][XHP] staging buf 0
    half*  xh1  = (half*)(smem + OFF_XH1);        // [64][XHP] staging buf 1
    half*  Ksh  = (half*)(smem + OFF_KS);         // [64][XPAD]
    half*  VshT = (half*)(smem + OFF_VS);         // [64][XPAD] transposed V
    float* xq   = (float*)(smem + OFF_R);         // Q-phase overlay [16][257]
    float* wqs  = (float*)(smem + OFF_R + 16448); // [16][68]
    half*  qbuf = (half*)(smem + OFF_R);          // Q-bounce [4][32][XPAD]
    float* ws   = (float*)(smem + OFF_R);         // out-proj overlay [64][68]
    float* Osh  = (float*)(smem);                 // [256][OPAD] overlays wh (dead)

    int tid = threadIdx.x;
    int warp = tid >> 5, lane = tid & 31;
    int bh = blockIdx.y;
    int b = bh / NH, h = bh % NH;
    int q0 = blockIdx.x * QT;

    // ---- Stage K/V weights once: fp32 gmem -> fp16 smem ----
    for (int e = tid; e < 128 * 192; e += 256) {
        int n = e / 192, c4 = (e % 192) << 2;
        int grow = (n < 64) ? (CH + h * HD + n) : (2 * CH + h * HD + n - 64);
        float4 t = *(const float4*)&w[grow * CH + c4];
        half2* dst = (half2*)&wh[n * WPAD + c4];
        dst[0] = __floats2half2_rn(t.x, t.y);
        dst[1] = __floats2half2_rn(t.z, t.w);
    }

    // ---- Phase 1: scalar Q-proj (proven), row tid, scaled by hd^-0.5 ----
    float qreg[HD];
#pragma unroll
    for (int d = 0; d < HD; d++) qreg[d] = 0.f;

    for (int k0 = 0; k0 < CH; k0 += 16) {
        __syncthreads();
#pragma unroll
        for (int i = 0; i < 16; i++) {
            int e = tid + 256 * i;
            int r = e >> 4, kk = e & 15;
            xq[kk * 257 + r] = x[(b * SEQ + q0 + r) * CH + k0 + kk];
        }
#pragma unroll
        for (int i = 0; i < 4; i++) {
            int e = tid + 256 * i;
            int d = e >> 4, kk = e & 15;
            wqs[kk * 68 + d] = w[(h * HD + d) * CH + k0 + kk];
        }
        __syncthreads();
#pragma unroll
        for (int kk = 0; kk < 16; kk++) {
            float xv = xq[kk * 257 + tid];
#pragma unroll
            for (int dd = 0; dd < 16; dd++) {
                float4 w4 = *(const float4*)&wqs[kk * 68 + 4 * dd];
                qreg[4 * dd + 0] += xv * w4.x;
                qreg[4 * dd + 1] += xv * w4.y;
                qreg[4 * dd + 2] += xv * w4.z;
                qreg[4 * dd + 3] += xv * w4.w;
            }
        }
    }
#pragma unroll
    for (int d = 0; d < HD; d++) qreg[d] *= 0.125f;

    // ---- Convert Q rows -> persistent A-fragments (smem bounce, 2 passes) ----
    unsigned int qA[2][4][4];
#pragma unroll 1
    for (int pass = 0; pass < 2; pass++) {
        __syncthreads();
        if ((warp >> 2) == pass) {
            half* qb = qbuf + (warp & 3) * 32 * XPAD;
#pragma unroll
            for (int d = 0; d < HD; d += 2)
                *(half2*)&qb[lane * XPAD + d] = __floats2half2_rn(qreg[d], qreg[d + 1]);
        }
        __syncthreads();
        if ((warp >> 2) == pass) {
            half* qb = qbuf + (warp & 3) * 32 * XPAD;
#pragma unroll
            for (int mt = 0; mt < 2; mt++)
#pragma unroll
                for (int kt = 0; kt < 4; kt++)
                    ldm_x4(qA[mt][kt],
                           &qb[(mt * 16 + (lane & 15)) * XPAD + kt * 16 + ((lane >> 4) << 3)]);
        }
    }
    __syncthreads();   // qbuf reads done before xh0 staging overlays it

    // ---- Main loop over 64-key blocks ----
    float mrow[4], lrow[4], ofr[2][8][4];
#pragma unroll
    for (int i = 0; i < 4; i++) { mrow[i] = -1e30f; lrow[i] = 0.f; }
#pragma unroll
    for (int mt = 0; mt < 2; mt++)
#pragma unroll
        for (int nt = 0; nt < 8; nt++)
#pragma unroll
            for (int q = 0; q < 4; q++) ofr[mt][nt][q] = 0.f;

    // Prefetch chunk 0 of kblock 0
    float4 pre[3];
#pragma unroll
    for (int i = 0; i < 3; i++) {
        int e = tid + 256 * i;
        int r = e / 12, c4 = (e % 12) << 2;
        pre[i] = *(const float4*)&x[(b * SEQ + 0 + r) * CH + 0 + c4];
    }

    for (int kb = 0; kb < SEQ; kb += KB) {
        // Store prefetched chunk 0 into xh0 (visible after ch=0's sync)
#pragma unroll
        for (int i = 0; i < 3; i++) {
            int e = tid + 256 * i;
            int r = e / 12, c4 = (e % 12) << 2;
            half2* dst = (half2*)&xh0[r * XHP + c4];
            dst[0] = __floats2half2_rn(pre[i].x, pre[i].y);
            dst[1] = __floats2half2_rn(pre[i].z, pre[i].w);
        }

        float cfr[4][2][4];
#pragma unroll
        for (int mt = 0; mt < 4; mt++)
#pragma unroll
            for (int nt = 0; nt < 2; nt++)
#pragma unroll
                for (int q = 0; q < 4; q++) cfr[mt][nt][q] = 0.f;

        // 16 chunks of 48 k-dims, software-pipelined: prefetch ch+1 during mma(ch)
#pragma unroll 1
        for (int ch = 0; ch < 16; ch++) {
            __syncthreads();   // staged buffer visible; prev buffer reads done
            if (ch < 15) {
#pragma unroll
                for (int i = 0; i < 3; i++) {
                    int e = tid + 256 * i;
                    int r = e / 12, c4 = (e % 12) << 2;
                    pre[i] = *(const float4*)&x[(b * SEQ + kb + r) * CH + (ch + 1) * 48 + c4];
                }
            }
            half* cur = (ch & 1) ? xh1 : xh0;
#pragma unroll
            for (int kt = 0; kt < 3; kt++) {
                unsigned int afr[4][4], bfr[2][2];
#pragma unroll
                for (int mt = 0; mt < 4; mt++)
                    ldm_x4(afr[mt],
                           &cur[(mt * 16 + (lane & 15)) * XHP + kt * 16 + ((lane >> 4) << 3)]);
#pragma unroll
                for (int nt = 0; nt < 2; nt++) {
                    int l16 = lane & 15;
                    int row = warp * 16 + nt * 8 + (l16 & 7);
                    int kcol = ch * 48 + kt * 16 + ((l16 >> 3) << 3);
                    ldm_x2(bfr[nt], &wh[row * WPAD + kcol]);
                }
#pragma unroll
                for (int mt = 0; mt < 4; mt++)
#pragma unroll
                    for (int nt = 0; nt < 2; nt++)
                        mma16816(cfr[mt][nt], afr[mt], bfr[nt]);
            }
            if (ch < 15) {
                half* nxt = (ch & 1) ? xh0 : xh1;
#pragma unroll
                for (int i = 0; i < 3; i++) {
                    int e = tid + 256 * i;
                    int r = e / 12, c4 = (e % 12) << 2;
                    half2* dst = (half2*)&nxt[r * XHP + c4];
                    dst[0] = __floats2half2_rn(pre[i].x, pre[i].y);
                    dst[1] = __floats2half2_rn(pre[i].z, pre[i].w);
                }
            }
        }

        // Prefetch chunk 0 of the NEXT kblock (covered by epilogue/S/softmax/PV)
        {
            int nkb = (kb + KB < SEQ) ? kb + KB : kb;
#pragma unroll
            for (int i = 0; i < 3; i++) {
                int e = tid + 256 * i;
                int r = e / 12, c4 = (e % 12) << 2;
                pre[i] = *(const float4*)&x[(b * SEQ + nkb + r) * CH + 0 + c4];
            }
        }

        // --- Epilogue: K warps (0-3) -> Ksh[key][dim]; V warps (4-7) -> VshT[dim][key]
        if (warp < 4) {
            int d0 = warp * 16;
#pragma unroll
            for (int mt = 0; mt < 4; mt++)
#pragma unroll
                for (int nt = 0; nt < 2; nt++) {
                    int key = mt * 16 + (lane >> 2);
                    int dim = d0 + nt * 8 + ((lane & 3) << 1);
                    *(half2*)&Ksh[key * XPAD + dim] = __floats2half2_rn(cfr[mt][nt][0], cfr[mt][nt][1]);
                    *(half2*)&Ksh[(key + 8) * XPAD + dim] = __floats2half2_rn(cfr[mt][nt][2], cfr[mt][nt][3]);
                }
        } else {
            int d0 = (warp - 4) * 16;
#pragma unroll
            for (int mt = 0; mt < 4; mt++)
#pragma unroll
                for (int nt = 0; nt < 2; nt++) {
                    int key = mt * 16 + (lane >> 2);
                    int dim = d0 + nt * 8 + ((lane & 3) << 1);
                    VshT[dim * XPAD + key]           = __float2half(cfr[mt][nt][0]);
                    VshT[(dim + 1) * XPAD + key]     = __float2half(cfr[mt][nt][1]);
                    VshT[dim * XPAD + key + 8]       = __float2half(cfr[mt][nt][2]);
                    VshT[(dim + 1) * XPAD + key + 8] = __float2half(cfr[mt][nt][3]);
                }
        }
        __syncthreads();

        // --- S = Q @ K^T (32 q-rows per warp x 64 keys) ---
        float sfr[2][8][4];
#pragma unroll
        for (int mt = 0; mt < 2; mt++)
#pragma unroll
            for (int nt = 0; nt < 8; nt++)
#pragma unroll
                for (int q = 0; q < 4; q++) sfr[mt][nt][q] = 0.f;

        int g = lane >> 3;
#pragma unroll
        for (int kt = 0; kt < 4; kt++) {
            unsigned int bfr[8][2];
#pragma unroll
            for (int np = 0; np < 4; np++) {
                unsigned int r4[4];
                ldm_x4(r4, &Ksh[(np * 16 + (g & 1) * 8 + (lane & 7)) * XPAD
                                + kt * 16 + ((g >> 1) << 3)]);
                bfr[2 * np][0] = r4[0];     bfr[2 * np][1] = r4[2];
                bfr[2 * np + 1][0] = r4[1]; bfr[2 * np + 1][1] = r4[3];
            }
#pragma unroll
            for (int mt = 0; mt < 2; mt++)
#pragma unroll
                for (int nt = 0; nt < 8; nt++)
                    mma16816(sfr[mt][nt], qA[mt][kt], bfr[nt]);
        }

        // --- Online softmax in fragments (4 rows per lane, quad shuffles) ---
#pragma unroll
        for (int mt = 0; mt < 2; mt++)
#pragma unroll
            for (int hf = 0; hf < 2; hf++) {
                int ri = mt * 2 + hf;
                float mx = mrow[ri];
#pragma unroll
                for (int nt = 0; nt < 8; nt++)
                    mx = fmaxf(mx, fmaxf(sfr[mt][nt][hf * 2], sfr[mt][nt][hf * 2 + 1]));
                mx = fmaxf(mx, __shfl_xor_sync(0xffffffffu, mx, 1));
                mx = fmaxf(mx, __shfl_xor_sync(0xffffffffu, mx, 2));
                float c = __expf(mrow[ri] - mx);
                mrow[ri] = mx;
                float sum = 0.f;
#pragma unroll
                for (int nt = 0; nt < 8; nt++) {
                    float p0 = __expf(sfr[mt][nt][hf * 2] - mx);
                    float p1 = __expf(sfr[mt][nt][hf * 2 + 1] - mx);
                    sfr[mt][nt][hf * 2] = p0; sfr[mt][nt][hf * 2 + 1] = p1;
                    sum += p0 + p1;
                }
                sum += __shfl_xor_sync(0xffffffffu, sum, 1);
                sum += __shfl_xor_sync(0xffffffffu, sum, 2);
                lrow[ri] = lrow[ri] * c + sum;
#pragma unroll
                for (int nt = 0; nt < 8; nt++) {
                    ofr[mt][nt][hf * 2] *= c;
                    ofr[mt][nt][hf * 2 + 1] *= c;
                }
            }

        // --- P (fp16 A-frags) from S C-frags ---
        unsigned int pA[2][4][4];
#pragma unroll
        for (int mt = 0; mt < 2; mt++)
#pragma unroll
            for (int kt = 0; kt < 4; kt++) {
                pA[mt][kt][0] = pack_h2(sfr[mt][2 * kt][0], sfr[mt][2 * kt][1]);
                pA[mt][kt][1] = pack_h2(sfr[mt][2 * kt][2], sfr[mt][2 * kt][3]);
                pA[mt][kt][2] = pack_h2(sfr[mt][2 * kt + 1][0], sfr[mt][2 * kt + 1][1]);
                pA[mt][kt][3] = pack_h2(sfr[mt][2 * kt + 1][2], sfr[mt][2 * kt + 1][3]);
            }

        // --- O += P @ V (B-frags from VshT, non-trans ldmatrix) ---
#pragma unroll
        for (int kt = 0; kt < 4; kt++) {
            unsigned int bfr[8][2];
#pragma unroll
            for (int np = 0; np < 4; np++) {
                unsigned int r4[4];
                ldm_x4(r4, &VshT[(np * 16 + (g & 1) * 8 + (lane & 7)) * XPAD
                                 + kt * 16 + ((g >> 1) << 3)]);
                bfr[2 * np][0] = r4[0];     bfr[2 * np][1] = r4[2];
                bfr[2 * np + 1][0] = r4[1]; bfr[2 * np + 1][1] = r4[3];
            }
#pragma unroll
            for (int mt = 0; mt < 2; mt++)
#pragma unroll
                for (int nt = 0; nt < 8; nt++)
                    mma16816(ofr[mt][nt], pA[mt][kt], bfr[nt]);
        }
    }

    // ---- O fragments -> Osh (overlaying dead weight region), /l ----
    float inv[4];
#pragma unroll
    for (int i = 0; i < 4; i++) inv[i] = 1.0f / lrow[i];
#pragma unroll
    for (int mt = 0; mt < 2; mt++)
#pragma unroll
        for (int nt = 0; nt < 8; nt++) {
            int r = 32 * warp + mt * 16 + (lane >> 2);
            int c = nt * 8 + ((lane & 3) << 1);
            *(float2*)&Osh[r * OPAD + c] =
                make_float2(ofr[mt][nt][0] * inv[mt * 2], ofr[mt][nt][1] * inv[mt * 2]);
            *(float2*)&Osh[(r + 8) * OPAD + c] =
                make_float2(ofr[mt][nt][2] * inv[mt * 2 + 1], ofr[mt][nt][3] * inv[mt * 2 + 1]);
        }
    __syncthreads();

    float oreg[HD];
#pragma unroll
    for (int dd = 0; dd < 16; dd++) {
        float4 t = *(const float4*)&Osh[tid * OPAD + 4 * dd];
        oreg[4 * dd + 0] = t.x; oreg[4 * dd + 1] = t.y;
        oreg[4 * dd + 2] = t.z; oreg[4 * dd + 3] = t.w;
    }
    __syncthreads();

    // ---- Phase 3 (proven): project head slice, accumulate into out ----
    float* orow = out + (b * SEQ + q0 + tid) * CH;
    for (int j0 = 0; j0 < CH; j0 += 64) {
#pragma unroll
        for (int i = 0; i < 16; i++) {
            int e = tid + 256 * i;
            int d = e & 63, jj = e >> 6;
            ws[jj * 68 + d] = pw[(j0 + jj) * CH + h * HD + d];
        }
        __syncthreads();
#pragma unroll 4
        for (int jj = 0; jj < 64; jj++) {
            float acc = 0.f;
#pragma unroll
            for (int dd = 0; dd < 16; dd++) {
                float4 w4 = *(const float4*)&ws[jj * 68 + 4 * dd];
                acc += oreg[4 * dd + 0] * w4.x + oreg[4 * dd + 1] * w4.y
                     + oreg[4 * dd + 2] * w4.z + oreg[4 * dd + 3] * w4.w;
            }
            atomicAdd(orow + j0 + jj, acc);
        }
        __syncthreads();
    }
}

// ---------------------------------------------------------------------------

extern "C" void kernel_launch(void* const* d_in, const int* in_sizes, int n_in,
                              void* d_out, int out_size) {
    const float* x = 0; const float* qkv_w = 0;
    const float* proj_w = 0; const float* proj_b = 0;
    for (int i = 0; i < n_in; i++) {
        int s = in_sizes[i];
        const float* p = (const float*)d_in[i];
        if (s == NTOK * CH)        { if (!x) x = p; }
        else if (s == 3 * CH * CH) { if (!qkv_w) qkv_w = p; }
        else if (s == CH * CH)     { if (!proj_w) proj_w = p; }
        else if (s == CH)          { if (!proj_b) proj_b = p; }
    }
    if (!x || !qkv_w || !proj_w || !proj_b) {
        x      = (const float*)d_in[0];
        qkv_w  = (const float*)d_in[1];
        proj_w = (const float*)d_in[2];
        proj_b = (const float*)d_in[3];
    }
    float* out = (float*)d_out;

    static int smem_set = 0;
    if (!smem_set) {
        cudaFuncSetAttribute(fused_attn_kernel,
                             cudaFuncAttributeMaxDynamicSharedMemorySize, SMEM_TOTAL);
        smem_set = 1;
    }

    bias_init_kernel<<<(NTOK * CH + 255) / 256, 256>>>(proj_b, out, NTOK * CH);
    fused_attn_kernel<<<dim3(SEQ / QT, Bq * NH), 256, SMEM_TOTAL>>>(x, qkv_w, proj_w, out);
}

// round 11
// speedup vs baseline: 8.7298x; 1.5079x over previous
#include <cuda_runtime.h>
#include <cuda_fp16.h>
#include <cstdint>
#include <math.h>

#define Bq 4
#define SEQ 2048
#define CH 768
#define NH 12
#define HD 64
#define NTOK (Bq*SEQ)

#define KOFF 0
#define VOFF 6291456
#define QOFF 12582912

__device__ __forceinline__ void ldm_x4(unsigned int* r, const void* p) {
    unsigned int a = (unsigned int)__cvta_generic_to_shared(p);
    asm volatile("ldmatrix.sync.aligned.m8n8.x4.shared.b16 {%0,%1,%2,%3}, [%4];"
                 : "=r"(r[0]), "=r"(r[1]), "=r"(r[2]), "=r"(r[3]) : "r"(a));
}
__device__ __forceinline__ void ldm_x2(unsigned int* r, const void* p) {
    unsigned int a = (unsigned int)__cvta_generic_to_shared(p);
    asm volatile("ldmatrix.sync.aligned.m8n8.x2.shared.b16 {%0,%1}, [%2];"
                 : "=r"(r[0]), "=r"(r[1]) : "r"(a));
}
__device__ __forceinline__ void mma16816(float* c, const unsigned int* a,
                                         const unsigned int* b) {
    asm volatile("mma.sync.aligned.m16n8k16.row.col.f32.f16.f16.f32 "
                 "{%0,%1,%2,%3},{%4,%5,%6,%7},{%8,%9},{%0,%1,%2,%3};"
                 : "+f"(c[0]), "+f"(c[1]), "+f"(c[2]), "+f"(c[3])
                 : "r"(a[0]), "r"(a[1]), "r"(a[2]), "r"(a[3]), "r"(b[0]), "r"(b[1]));
}
__device__ __forceinline__ unsigned int pack_h2(float a, float b) {
    __half2 t = __floats2half2_rn(a, b);
    return *(unsigned int*)&t;
}

// ============ K1: QKV projection for one 6-head group ============
// CTA = (64 tokens, bhg). GEMM M=64, N=192(q|k|v of head h), K=768.
__global__ __launch_bounds__(256) void qkv_kernel(
    const float* __restrict__ x, const float* __restrict__ w,
    char* __restrict__ dout, int grp)
{
    extern __shared__ __align__(16) char sm[];
    half* Xs = (half*)sm;            // [64][56]
    half* Ws = (half*)(sm + 7168);   // [192][56]

    int tid = threadIdx.x, warp = tid >> 5, lane = tid & 31;
    int mw = warp >> 2, nw = warp & 3;
    int t0 = blockIdx.x * 64;
    int bhg = blockIdx.y, b = bhg / 6, hg = bhg % 6, h = grp * 6 + hg;

    float cfr[2][6][4];
#pragma unroll
    for (int mt = 0; mt < 2; mt++)
#pragma unroll
        for (int nt = 0; nt < 6; nt++)
#pragma unroll
            for (int q = 0; q < 4; q++) cfr[mt][nt][q] = 0.f;

#pragma unroll 1
    for (int ch = 0; ch < 16; ch++) {
        __syncthreads();
#pragma unroll
        for (int i = 0; i < 3; i++) {          // X: 64x48
            int e = tid + 256 * i; int r = e / 12, c4 = (e % 12) << 2;
            float4 t = *(const float4*)&x[(b * SEQ + t0 + r) * CH + ch * 48 + c4];
            half2* d = (half2*)&Xs[r * 56 + c4];
            d[0] = __floats2half2_rn(t.x, t.y); d[1] = __floats2half2_rn(t.z, t.w);
        }
#pragma unroll
        for (int i = 0; i < 9; i++) {          // W: 192x48
            int e = tid + 256 * i; int r = e / 12, c4 = (e % 12) << 2;
            int wrow = (r < 64) ? (h * HD + r)
                     : (r < 128) ? (CH + h * HD + r - 64)
                                 : (2 * CH + h * HD + r - 128);
            float4 t = *(const float4*)&w[wrow * CH + ch * 48 + c4];
            half2* d = (half2*)&Ws[r * 56 + c4];
            d[0] = __floats2half2_rn(t.x, t.y); d[1] = __floats2half2_rn(t.z, t.w);
        }
        __syncthreads();
#pragma unroll
        for (int kt = 0; kt < 3; kt++) {
            unsigned int afr[2][4], bfr[6][2];
            int l16 = lane & 15;
#pragma unroll
            for (int mt = 0; mt < 2; mt++)
                ldm_x4(afr[mt], &Xs[(mw * 32 + mt * 16 + l16) * 56 + kt * 16 + ((lane >> 4) << 3)]);
#pragma unroll
            for (int nt = 0; nt < 6; nt++)
                ldm_x2(bfr[nt], &Ws[(nw * 48 + nt * 8 + (l16 & 7)) * 56 + kt * 16 + ((l16 >> 3) << 3)]);
#pragma unroll
            for (int mt = 0; mt < 2; mt++)
#pragma unroll
                for (int nt = 0; nt < 6; nt++)
                    mma16816(cfr[mt][nt], afr[mt], bfr[nt]);
        }
    }

    half* qoh = (half*)(dout + QOFF);
    half* kh  = (half*)(dout + KOFF);
    half* vth = (half*)(dout + VOFF);
#pragma unroll
    for (int mt = 0; mt < 2; mt++)
#pragma unroll
        for (int nt = 0; nt < 6; nt++) {
            int row = mw * 32 + mt * 16 + (lane >> 2);
            int col = nw * 48 + nt * 8 + ((lane & 3) << 1);
            int typ = col >> 6, dim = col & 63;
#pragma unroll
            for (int rr = 0; rr < 2; rr++) {
                int tok = t0 + row + rr * 8;
                float v0 = cfr[mt][nt][rr * 2], v1 = cfr[mt][nt][rr * 2 + 1];
                if (typ == 0) {
                    *(half2*)&qoh[(b * SEQ + tok) * CH + grp * 384 + hg * 64 + dim] =
                        __floats2half2_rn(v0 * 0.125f, v1 * 0.125f);
                } else if (typ == 1) {
                    *(half2*)&kh[(bhg * SEQ + tok) * 64 + dim] = __floats2half2_rn(v0, v1);
                } else {
                    vth[(bhg * 64 + dim) * SEQ + tok]     = __float2half(v0);
                    vth[(bhg * 64 + dim + 1) * SEQ + tok] = __float2half(v1);
                }
            }
        }
}

// ============ K2: attention for one group (reads K/V/Q, O in place) ========
// CTA = (128 q-rows, bhg). Warp w owns q rows q0+w*16..+16.
__global__ __launch_bounds__(256) void attn_kernel(char* __restrict__ dout, int grp)
{
    extern __shared__ __align__(16) char sm[];
    half* Qs = (half*)sm;                        // [128][72]
    half* Kb[2] = { (half*)(sm + 18432), (half*)(sm + 27648) };   // [64][72]
    half* Vb[2] = { (half*)(sm + 36864), (half*)(sm + 46080) };   // [64][72] (V^T)

    int tid = threadIdx.x, warp = tid >> 5, lane = tid & 31;
    int bhg = blockIdx.y, b = bhg / 6, hg = bhg % 6;
    int q0 = blockIdx.x * 128;
    half* qoh = (half*)(dout + QOFF);
    const half* kh  = (const half*)(dout + KOFF);
    const half* vth = (const half*)(dout + VOFF);

    // Stage Q (fp16, already scaled): 128 rows x 64 halves
#pragma unroll
    for (int i = 0; i < 4; i++) {
        int e = tid + 256 * i; int r = e >> 3, c = e & 7;
        ((uint4*)&Qs[r * 72])[c] =
            ((const uint4*)&qoh[(b * SEQ + q0 + r) * CH + grp * 384 + hg * 64])[c];
    }
    // Stage kblock 0 K/V
#pragma unroll
    for (int i = 0; i < 2; i++) {
        int e = tid + 256 * i; int r = e >> 3, c = e & 7;
        ((uint4*)&Kb[0][r * 72])[c] = ((const uint4*)&kh[(bhg * SEQ + r) * 64])[c];
        ((uint4*)&Vb[0][r * 72])[c] = ((const uint4*)&vth[(bhg * 64 + r) * SEQ])[c];
    }
    __syncthreads();

    unsigned int qA[4][4];
#pragma unroll
    for (int kt = 0; kt < 4; kt++)
        ldm_x4(qA[kt], &Qs[(warp * 16 + (lane & 15)) * 72 + kt * 16 + ((lane >> 4) << 3)]);

    float mrow[2] = {-1e30f, -1e30f}, lrow[2] = {0.f, 0.f}, ofr[8][4];
#pragma unroll
    for (int nt = 0; nt < 8; nt++)
#pragma unroll
        for (int q = 0; q < 4; q++) ofr[nt][q] = 0.f;

    int g = lane >> 3;
#pragma unroll 1
    for (int it = 0; it < 32; it++) {
        __syncthreads();
        uint4 pk[2], pv[2];
        if (it < 31) {
            int kb2 = (it + 1) * 64;
#pragma unroll
            for (int i = 0; i < 2; i++) {
                int e = tid + 256 * i; int r = e >> 3, c = e & 7;
                pk[i] = ((const uint4*)&kh[(bhg * SEQ + kb2 + r) * 64])[c];
                pv[i] = ((const uint4*)&vth[(bhg * 64 + r) * SEQ + kb2])[c];
            }
        }
        half* Kc = Kb[it & 1]; half* Vc = Vb[it & 1];

        float sfr[8][4];
#pragma unroll
        for (int nt = 0; nt < 8; nt++)
#pragma unroll
            for (int q = 0; q < 4; q++) sfr[nt][q] = 0.f;
#pragma unroll
        for (int kt = 0; kt < 4; kt++) {
            unsigned int bfr[8][2];
#pragma unroll
            for (int np = 0; np < 4; np++) {
                unsigned int r4[4];
                ldm_x4(r4, &Kc[(np * 16 + (g & 1) * 8 + (lane & 7)) * 72 + kt * 16 + ((g >> 1) << 3)]);
                bfr[2 * np][0] = r4[0];     bfr[2 * np][1] = r4[2];
                bfr[2 * np + 1][0] = r4[1]; bfr[2 * np + 1][1] = r4[3];
            }
#pragma unroll
            for (int nt = 0; nt < 8; nt++) mma16816(sfr[nt], qA[kt], bfr[nt]);
        }
#pragma unroll
        for (int hf = 0; hf < 2; hf++) {
            float mx = mrow[hf];
#pragma unroll
            for (int nt = 0; nt < 8; nt++)
                mx = fmaxf(mx, fmaxf(sfr[nt][hf * 2], sfr[nt][hf * 2 + 1]));
            mx = fmaxf(mx, __shfl_xor_sync(0xffffffffu, mx, 1));
            mx = fmaxf(mx, __shfl_xor_sync(0xffffffffu, mx, 2));
            float c = __expf(mrow[hf] - mx); mrow[hf] = mx;
            float sum = 0.f;
#pragma unroll
            for (int nt = 0; nt < 8; nt++) {
                float p0 = __expf(sfr[nt][hf * 2] - mx);
                float p1 = __expf(sfr[nt][hf * 2 + 1] - mx);
                sfr[nt][hf * 2] = p0; sfr[nt][hf * 2 + 1] = p1; sum += p0 + p1;
            }
            sum += __shfl_xor_sync(0xffffffffu, sum, 1);
            sum += __shfl_xor_sync(0xffffffffu, sum, 2);
            lrow[hf] = lrow[hf] * c + sum;
#pragma unroll
            for (int nt = 0; nt < 8; nt++) {
                ofr[nt][hf * 2] *= c; ofr[nt][hf * 2 + 1] *= c;
            }
        }
        unsigned int pA[4][4];
#pragma unroll
        for (int kt = 0; kt < 4; kt++) {
            pA[kt][0] = pack_h2(sfr[2 * kt][0], sfr[2 * kt][1]);
            pA[kt][1] = pack_h2(sfr[2 * kt][2], sfr[2 * kt][3]);
            pA[kt][2] = pack_h2(sfr[2 * kt + 1][0], sfr[2 * kt + 1][1]);
            pA[kt][3] = pack_h2(sfr[2 * kt + 1][2], sfr[2 * kt + 1][3]);
        }
#pragma unroll
        for (int kt = 0; kt < 4; kt++) {
            unsigned int bfr[8][2];
#pragma unroll
            for (int np = 0; np < 4; np++) {
                unsigned int r4[4];
                ldm_x4(r4, &Vc[(np * 16 + (g & 1) * 8 + (lane & 7)) * 72 + kt * 16 + ((g >> 1) << 3)]);
                bfr[2 * np][0] = r4[0];     bfr[2 * np][1] = r4[2];
                bfr[2 * np + 1][0] = r4[1]; bfr[2 * np + 1][1] = r4[3];
            }
#pragma unroll
            for (int nt = 0; nt < 8; nt++) mma16816(ofr[nt], pA[kt], bfr[nt]);
        }
        if (it < 31) {
            half* Kn = Kb[(it + 1) & 1]; half* Vn = Vb[(it + 1) & 1];
#pragma unroll
            for (int i = 0; i < 2; i++) {
                int e = tid + 256 * i; int r = e >> 3, c = e & 7;
                ((uint4*)&Kn[r * 72])[c] = pk[i];
                ((uint4*)&Vn[r * 72])[c] = pv[i];
            }
        }
    }

    float inv[2] = {1.0f / lrow[0], 1.0f / lrow[1]};
#pragma unroll
    for (int nt = 0; nt < 8; nt++) {
        int row = warp * 16 + (lane >> 2);
        int col = nt * 8 + ((lane & 3) << 1);
#pragma unroll
        for (int rr = 0; rr < 2; rr++) {
            int gt = b * SEQ + q0 + row + rr * 8;
            *(half2*)&qoh[gt * CH + grp * 384 + hg * 64 + col] =
                __floats2half2_rn(ofr[nt][rr * 2] * inv[rr], ofr[nt][rr * 2 + 1] * inv[rr]);
        }
    }
}

// ============ K3: out-proj, row range [rowBeg,rowEnd) ============
__global__ __launch_bounds__(256) void outproj_kernel(
    const float* __restrict__ pw, const float* __restrict__ bias,
    char* __restrict__ dout, int rowBeg, int rowEnd)
{
    extern __shared__ __align__(16) char sm[];
    half*  Oh = (half*)sm;                // [64][776]
    half*  Pw = (half*)(sm + 99328);      // [256][56]
    float* bs = (float*)(sm + 128000);    // [768]

    int tid = threadIdx.x, warp = tid >> 5, lane = tid & 31;
    int mw = warp >> 2, nw = warp & 3;
    int r0 = rowBeg + blockIdx.x * 64;
    const half* qo = (const half*)(dout + QOFF);
    float* out = (float*)dout;

    // Stage the CTA's O tile FIRST (read-before-any-write)
#pragma unroll
    for (int i = 0; i < 24; i++) {
        int e = tid + 256 * i; int r = e / 96, c = e % 96;
        int rr = r0 + r; if (rr > NTOK - 1) rr = NTOK - 1;
        ((uint4*)&Oh[r * 776])[c] = ((const uint4*)&qo[rr * CH])[c];
    }
#pragma unroll
    for (int i = 0; i < 3; i++) bs[tid + 256 * i] = bias[tid + 256 * i];
    __syncthreads();

#pragma unroll 1
    for (int nc = 0; nc < 3; nc++) {
        float cfr[2][8][4];
#pragma unroll
        for (int mt = 0; mt < 2; mt++)
#pragma unroll
            for (int nt = 0; nt < 8; nt++)
#pragma unroll
                for (int q = 0; q < 4; q++) cfr[mt][nt][q] = 0.f;
#pragma unroll 1
        for (int ch = 0; ch < 16; ch++) {
            __syncthreads();
#pragma unroll
            for (int i = 0; i < 12; i++) {
                int e = tid + 256 * i; int r = e / 12, c4 = (e % 12) << 2;
                float4 t = *(const float4*)&pw[(nc * 256 + r) * CH + ch * 48 + c4];
                half2* d = (half2*)&Pw[r * 56 + c4];
                d[0] = __floats2half2_rn(t.x, t.y); d[1] = __floats2half2_rn(t.z, t.w);
            }
            __syncthreads();
#pragma unroll
            for (int kt = 0; kt < 3; kt++) {
                unsigned int afr[2][4], bfr[8][2];
                int l16 = lane & 15;
#pragma unroll
                for (int mt = 0; mt < 2; mt++)
                    ldm_x4(afr[mt], &Oh[(mw * 32 + mt * 16 + l16) * 776 + ch * 48 + kt * 16 + ((lane >> 4) << 3)]);
#pragma unroll
                for (int nt = 0; nt < 8; nt++)
                    ldm_x2(bfr[nt], &Pw[(nw * 64 + nt * 8 + (l16 & 7)) * 56 + kt * 16 + ((l16 >> 3) << 3)]);
#pragma unroll
                for (int mt = 0; mt < 2; mt++)
#pragma unroll
                    for (int nt = 0; nt < 8; nt++)
                        mma16816(cfr[mt][nt], afr[mt], bfr[nt]);
            }
        }
#pragma unroll
        for (int mt = 0; mt < 2; mt++)
#pragma unroll
            for (int nt = 0; nt < 8; nt++) {
                int row = mw * 32 + mt * 16 + (lane >> 2);
                int col = nc * 256 + nw * 64 + nt * 8 + ((lane & 3) << 1);
#pragma unroll
                for (int rr = 0; rr < 2; rr++) {
                    int gr = r0 + row + rr * 8;
                    if (gr < rowEnd) {
                        float2 st = make_float2(cfr[mt][nt][rr * 2] + bs[col],
                                                cfr[mt][nt][rr * 2 + 1] + bs[col + 1]);
                        *(float2*)&out[gr * CH + col] = st;
                    }
                }
            }
    }
}

// ---------------------------------------------------------------------------
extern "C" void kernel_launch(void* const* d_in, const int* in_sizes, int n_in,
                              void* d_out, int out_size) {
    const float* x = 0; const float* qkv_w = 0;
    const float* proj_w = 0; const float* proj_b = 0;
    for (int i = 0; i < n_in; i++) {
        int s = in_sizes[i];
        const float* p = (const float*)d_in[i];
        if (s == NTOK * CH)        { if (!x) x = p; }
        else if (s == 3 * CH * CH) { if (!qkv_w) qkv_w = p; }
        else if (s == CH * CH)     { if (!proj_w) proj_w = p; }
        else if (s == CH)          { if (!proj_b) proj_b = p; }
    }
    if (!x || !qkv_w || !proj_w || !proj_b) {
        x = (const float*)d_in[0]; qkv_w = (const float*)d_in[1];
        proj_w = (const float*)d_in[2]; proj_b = (const float*)d_in[3];
    }
    char* dout = (char*)d_out;

    static int done = 0;
    if (!done) {
        cudaFuncSetAttribute(attn_kernel, cudaFuncAttributeMaxDynamicSharedMemorySize, 55296);
        cudaFuncSetAttribute(outproj_kernel, cudaFuncAttributeMaxDynamicSharedMemorySize, 131072);
        done = 1;
    }

    for (int grp = 0; grp < 2; grp++) {
        qkv_kernel<<<dim3(SEQ / 64, 24), 256, 28672>>>(x, qkv_w, dout, grp);
        attn_kernel<<<dim3(SEQ / 128, 24), 256, 55296>>>(dout, grp);
    }
    const int rs[15] = {0, 4096, 6144, 7168, 7680, 7936, 8064, 8128,
                        8160, 8176, 8184, 8188, 8190, 8191, 8192};
    for (int i = 0; i < 14; i++) {
        int a = rs[i], bnd = rs[i + 1];
        outproj_kernel<<<(bnd - a + 63) / 64, 256, 131072>>>(proj_w, proj_b, dout, a, bnd);
    }
}

// round 12
// speedup vs baseline: 12.5558x; 1.4383x over previous
#include <cuda_runtime.h>
#include <cuda_fp16.h>
#include <cstdint>
#include <math.h>

#define Bq 4
#define SEQ 2048
#define CH 768
#define NH 12
#define HD 64
#define NTOK (Bq*SEQ)

#define KOFF 0
#define VOFF 6291456
#define QOFF 12582912

__device__ __forceinline__ void ldm_x4(unsigned int* r, const void* p) {
    unsigned int a = (unsigned int)__cvta_generic_to_shared(p);
    asm volatile("ldmatrix.sync.aligned.m8n8.x4.shared.b16 {%0,%1,%2,%3}, [%4];"
                 : "=r"(r[0]), "=r"(r[1]), "=r"(r[2]), "=r"(r[3]) : "r"(a));
}
__device__ __forceinline__ void ldm_x2(unsigned int* r, const void* p) {
    unsigned int a = (unsigned int)__cvta_generic_to_shared(p);
    asm volatile("ldmatrix.sync.aligned.m8n8.x2.shared.b16 {%0,%1}, [%2];"
                 : "=r"(r[0]), "=r"(r[1]) : "r"(a));
}
__device__ __forceinline__ void mma16816(float* c, const unsigned int* a,
                                         const unsigned int* b) {
    asm volatile("mma.sync.aligned.m16n8k16.row.col.f32.f16.f16.f32 "
                 "{%0,%1,%2,%3},{%4,%5,%6,%7},{%8,%9},{%0,%1,%2,%3};"
                 : "+f"(c[0]), "+f"(c[1]), "+f"(c[2]), "+f"(c[3])
                 : "r"(a[0]), "r"(a[1]), "r"(a[2]), "r"(a[3]), "r"(b[0]), "r"(b[1]));
}
__device__ __forceinline__ unsigned int pack_h2(float a, float b) {
    __half2 t = __floats2half2_rn(a, b);
    return *(unsigned int*)&t;
}

// ============ K1: QKV projection, one 6-head group, pipelined staging ======
__global__ __launch_bounds__(256) void qkv_kernel(
    const float* __restrict__ x, const float* __restrict__ w,
    char* __restrict__ dout, int grp)
{
    extern __shared__ __align__(16) char sm[];   // 2 bufs of {Xs[64][56], Ws[192][56]}
    int tid = threadIdx.x, warp = tid >> 5, lane = tid & 31;
    int mw = warp >> 2, nw = warp & 3;
    int t0 = blockIdx.x * 64;
    int bhg = blockIdx.y, b = bhg / 6, hg = bhg % 6, h = grp * 6 + hg;

    int rX[3], cX[3], rW[9], cW[9], wr[9];
#pragma unroll
    for (int i = 0; i < 3; i++) { int e = tid + 256 * i; rX[i] = e / 12; cX[i] = (e % 12) << 2; }
#pragma unroll
    for (int i = 0; i < 9; i++) {
        int e = tid + 256 * i; int r = e / 12; rW[i] = r; cW[i] = (e % 12) << 2;
        wr[i] = (r < 64) ? (h * HD + r) : (r < 128) ? (CH + h * HD + r - 64)
                                                    : (2 * CH + h * HD + r - 128);
    }

    float4 pX[3], pW[9];
#pragma unroll
    for (int i = 0; i < 3; i++) pX[i] = *(const float4*)&x[(b * SEQ + t0 + rX[i]) * CH + cX[i]];
#pragma unroll
    for (int i = 0; i < 9; i++) pW[i] = *(const float4*)&w[wr[i] * CH + cW[i]];
    {
        half* Xs = (half*)sm; half* Ws = (half*)(sm + 7168);
#pragma unroll
        for (int i = 0; i < 3; i++) { half2* d = (half2*)&Xs[rX[i] * 56 + cX[i]];
            d[0] = __floats2half2_rn(pX[i].x, pX[i].y); d[1] = __floats2half2_rn(pX[i].z, pX[i].w); }
#pragma unroll
        for (int i = 0; i < 9; i++) { half2* d = (half2*)&Ws[rW[i] * 56 + cW[i]];
            d[0] = __floats2half2_rn(pW[i].x, pW[i].y); d[1] = __floats2half2_rn(pW[i].z, pW[i].w); }
    }

    float cfr[2][6][4];
#pragma unroll
    for (int mt = 0; mt < 2; mt++)
#pragma unroll
        for (int nt = 0; nt < 6; nt++)
#pragma unroll
            for (int q = 0; q < 4; q++) cfr[mt][nt][q] = 0.f;

#pragma unroll 1
    for (int ch = 0; ch < 16; ch++) {
        __syncthreads();
        if (ch < 15) {
#pragma unroll
            for (int i = 0; i < 3; i++)
                pX[i] = *(const float4*)&x[(b * SEQ + t0 + rX[i]) * CH + (ch + 1) * 48 + cX[i]];
#pragma unroll
            for (int i = 0; i < 9; i++)
                pW[i] = *(const float4*)&w[wr[i] * CH + (ch + 1) * 48 + cW[i]];
        }
        half* Xc = (half*)(sm + (ch & 1) * 28672);
        half* Wc = (half*)(sm + (ch & 1) * 28672 + 7168);
#pragma unroll
        for (int kt = 0; kt < 3; kt++) {
            unsigned int afr[2][4], bfr[6][2];
            int l16 = lane & 15;
#pragma unroll
            for (int mt = 0; mt < 2; mt++)
                ldm_x4(afr[mt], &Xc[(mw * 32 + mt * 16 + l16) * 56 + kt * 16 + ((lane >> 4) << 3)]);
#pragma unroll
            for (int nt = 0; nt < 6; nt++)
                ldm_x2(bfr[nt], &Wc[(nw * 48 + nt * 8 + (l16 & 7)) * 56 + kt * 16 + ((l16 >> 3) << 3)]);
#pragma unroll
            for (int mt = 0; mt < 2; mt++)
#pragma unroll
                for (int nt = 0; nt < 6; nt++)
                    mma16816(cfr[mt][nt], afr[mt], bfr[nt]);
        }
        if (ch < 15) {
            half* Xn = (half*)(sm + ((ch + 1) & 1) * 28672);
            half* Wn = (half*)(sm + ((ch + 1) & 1) * 28672 + 7168);
#pragma unroll
            for (int i = 0; i < 3; i++) { half2* d = (half2*)&Xn[rX[i] * 56 + cX[i]];
                d[0] = __floats2half2_rn(pX[i].x, pX[i].y); d[1] = __floats2half2_rn(pX[i].z, pX[i].w); }
#pragma unroll
            for (int i = 0; i < 9; i++) { half2* d = (half2*)&Wn[rW[i] * 56 + cW[i]];
                d[0] = __floats2half2_rn(pW[i].x, pW[i].y); d[1] = __floats2half2_rn(pW[i].z, pW[i].w); }
        }
    }

    half* qoh = (half*)(dout + QOFF);
    half* kh  = (half*)(dout + KOFF);
    half* vth = (half*)(dout + VOFF);
#pragma unroll
    for (int mt = 0; mt < 2; mt++)
#pragma unroll
        for (int nt = 0; nt < 6; nt++) {
            int row = mw * 32 + mt * 16 + (lane >> 2);
            int col = nw * 48 + nt * 8 + ((lane & 3) << 1);
            int typ = col >> 6, dim = col & 63;
#pragma unroll
            for (int rr = 0; rr < 2; rr++) {
                int tok = t0 + row + rr * 8;
                float v0 = cfr[mt][nt][rr * 2], v1 = cfr[mt][nt][rr * 2 + 1];
                if (typ == 0) {
                    *(half2*)&qoh[(b * SEQ + tok) * CH + grp * 384 + hg * 64 + dim] =
                        __floats2half2_rn(v0 * 0.125f, v1 * 0.125f);
                } else if (typ == 1) {
                    *(half2*)&kh[(bhg * SEQ + tok) * 64 + dim] = __floats2half2_rn(v0, v1);
                } else {
                    vth[(bhg * 64 + dim) * SEQ + tok]     = __float2half(v0);
                    vth[(bhg * 64 + dim + 1) * SEQ + tok] = __float2half(v1);
                }
            }
        }
}

// ============ K2: attention (PROVEN R11 code, unchanged) ============
__global__ __launch_bounds__(256) void attn_kernel(char* __restrict__ dout, int grp)
{
    extern __shared__ __align__(16) char sm[];
    half* Qs = (half*)sm;
    half* Kb[2] = { (half*)(sm + 18432), (half*)(sm + 27648) };
    half* Vb[2] = { (half*)(sm + 36864), (half*)(sm + 46080) };

    int tid = threadIdx.x, warp = tid >> 5, lane = tid & 31;
    int bhg = blockIdx.y, b = bhg / 6, hg = bhg % 6;
    int q0 = blockIdx.x * 128;
    half* qoh = (half*)(dout + QOFF);
    const half* kh  = (const half*)(dout + KOFF);
    const half* vth = (const half*)(dout + VOFF);

#pragma unroll
    for (int i = 0; i < 4; i++) {
        int e = tid + 256 * i; int r = e >> 3, c = e & 7;
        ((uint4*)&Qs[r * 72])[c] =
            ((const uint4*)&qoh[(b * SEQ + q0 + r) * CH + grp * 384 + hg * 64])[c];
    }
#pragma unroll
    for (int i = 0; i < 2; i++) {
        int e = tid + 256 * i; int r = e >> 3, c = e & 7;
        ((uint4*)&Kb[0][r * 72])[c] = ((const uint4*)&kh[(bhg * SEQ + r) * 64])[c];
        ((uint4*)&Vb[0][r * 72])[c] = ((const uint4*)&vth[(bhg * 64 + r) * SEQ])[c];
    }
    __syncthreads();

    unsigned int qA[4][4];
#pragma unroll
    for (int kt = 0; kt < 4; kt++)
        ldm_x4(qA[kt], &Qs[(warp * 16 + (lane & 15)) * 72 + kt * 16 + ((lane >> 4) << 3)]);

    float mrow[2] = {-1e30f, -1e30f}, lrow[2] = {0.f, 0.f}, ofr[8][4];
#pragma unroll
    for (int nt = 0; nt < 8; nt++)
#pragma unroll
        for (int q = 0; q < 4; q++) ofr[nt][q] = 0.f;

    int g = lane >> 3;
#pragma unroll 1
    for (int it = 0; it < 32; it++) {
        __syncthreads();
        uint4 pk[2], pv[2];
        if (it < 31) {
            int kb2 = (it + 1) * 64;
#pragma unroll
            for (int i = 0; i < 2; i++) {
                int e = tid + 256 * i; int r = e >> 3, c = e & 7;
                pk[i] = ((const uint4*)&kh[(bhg * SEQ + kb2 + r) * 64])[c];
                pv[i] = ((const uint4*)&vth[(bhg * 64 + r) * SEQ + kb2])[c];
            }
        }
        half* Kc = Kb[it & 1]; half* Vc = Vb[it & 1];

        float sfr[8][4];
#pragma unroll
        for (int nt = 0; nt < 8; nt++)
#pragma unroll
            for (int q = 0; q < 4; q++) sfr[nt][q] = 0.f;
#pragma unroll
        for (int kt = 0; kt < 4; kt++) {
            unsigned int bfr[8][2];
#pragma unroll
            for (int np = 0; np < 4; np++) {
                unsigned int r4[4];
                ldm_x4(r4, &Kc[(np * 16 + (g & 1) * 8 + (lane & 7)) * 72 + kt * 16 + ((g >> 1) << 3)]);
                bfr[2 * np][0] = r4[0];     bfr[2 * np][1] = r4[2];
                bfr[2 * np + 1][0] = r4[1]; bfr[2 * np + 1][1] = r4[3];
            }
#pragma unroll
            for (int nt = 0; nt < 8; nt++) mma16816(sfr[nt], qA[kt], bfr[nt]);
        }
#pragma unroll
        for (int hf = 0; hf < 2; hf++) {
            float mx = mrow[hf];
#pragma unroll
            for (int nt = 0; nt < 8; nt++)
                mx = fmaxf(mx, fmaxf(sfr[nt][hf * 2], sfr[nt][hf * 2 + 1]));
            mx = fmaxf(mx, __shfl_xor_sync(0xffffffffu, mx, 1));
            mx = fmaxf(mx, __shfl_xor_sync(0xffffffffu, mx, 2));
            float c = __expf(mrow[hf] - mx); mrow[hf] = mx;
            float sum = 0.f;
#pragma unroll
            for (int nt = 0; nt < 8; nt++) {
                float p0 = __expf(sfr[nt][hf * 2] - mx);
                float p1 = __expf(sfr[nt][hf * 2 + 1] - mx);
                sfr[nt][hf * 2] = p0; sfr[nt][hf * 2 + 1] = p1; sum += p0 + p1;
            }
            sum += __shfl_xor_sync(0xffffffffu, sum, 1);
            sum += __shfl_xor_sync(0xffffffffu, sum, 2);
            lrow[hf] = lrow[hf] * c + sum;
#pragma unroll
            for (int nt = 0; nt < 8; nt++) {
                ofr[nt][hf * 2] *= c; ofr[nt][hf * 2 + 1] *= c;
            }
        }
        unsigned int pA[4][4];
#pragma unroll
        for (int kt = 0; kt < 4; kt++) {
            pA[kt][0] = pack_h2(sfr[2 * kt][0], sfr[2 * kt][1]);
            pA[kt][1] = pack_h2(sfr[2 * kt][2], sfr[2 * kt][3]);
            pA[kt][2] = pack_h2(sfr[2 * kt + 1][0], sfr[2 * kt + 1][1]);
            pA[kt][3] = pack_h2(sfr[2 * kt + 1][2], sfr[2 * kt + 1][3]);
        }
#pragma unroll
        for (int kt = 0; kt < 4; kt++) {
            unsigned int bfr[8][2];
#pragma unroll
            for (int np = 0; np < 4; np++) {
                unsigned int r4[4];
                ldm_x4(r4, &Vc[(np * 16 + (g & 1) * 8 + (lane & 7)) * 72 + kt * 16 + ((g >> 1) << 3)]);
                bfr[2 * np][0] = r4[0];     bfr[2 * np][1] = r4[2];
                bfr[2 * np + 1][0] = r4[1]; bfr[2 * np + 1][1] = r4[3];
            }
#pragma unroll
            for (int nt = 0; nt < 8; nt++) mma16816(ofr[nt], pA[kt], bfr[nt]);
        }
        if (it < 31) {
            half* Kn = Kb[(it + 1) & 1]; half* Vn = Vb[(it + 1) & 1];
#pragma unroll
            for (int i = 0; i < 2; i++) {
                int e = tid + 256 * i; int r = e >> 3, c = e & 7;
                ((uint4*)&Kn[r * 72])[c] = pk[i];
                ((uint4*)&Vn[r * 72])[c] = pv[i];
            }
        }
    }

    float inv[2] = {1.0f / lrow[0], 1.0f / lrow[1]};
#pragma unroll
    for (int nt = 0; nt < 8; nt++) {
        int row = warp * 16 + (lane >> 2);
        int col = nt * 8 + ((lane & 3) << 1);
#pragma unroll
        for (int rr = 0; rr < 2; rr++) {
            int gt = b * SEQ + q0 + row + rr * 8;
            *(half2*)&qoh[gt * CH + grp * 384 + hg * 64 + col] =
                __floats2half2_rn(ofr[nt][rr * 2] * inv[rr], ofr[nt][rr * 2 + 1] * inv[rr]);
        }
    }
}

// ============ K3: out-proj with pipelined weight staging ============
__global__ __launch_bounds__(256) void outproj_kernel(
    const float* __restrict__ pw, const float* __restrict__ bias,
    char* __restrict__ dout, int rowBeg, int rowEnd)
{
    extern __shared__ __align__(16) char sm[];
    half*  Oh = (half*)sm;                 // [64][776] = 99328 B
    float* bs = (float*)(sm + 156672);     // [768]
    // Pw bufs: sm + 99328 + buf*28672, each [256][56]

    int tid = threadIdx.x, warp = tid >> 5, lane = tid & 31;
    int mw = warp >> 2, nw = warp & 3;
    int r0 = rowBeg + blockIdx.x * 64;
    const half* qo = (const half*)(dout + QOFF);
    float* out = (float*)dout;

#pragma unroll
    for (int i = 0; i < 24; i++) {
        int e = tid + 256 * i; int r = e / 96, c = e % 96;
        int rr = r0 + r; if (rr > NTOK - 1) rr = NTOK - 1;
        ((uint4*)&Oh[r * 776])[c] = ((const uint4*)&qo[rr * CH])[c];
    }
#pragma unroll
    for (int i = 0; i < 3; i++) bs[tid + 256 * i] = bias[tid + 256 * i];

    int rP[12], cP[12];
#pragma unroll
    for (int i = 0; i < 12; i++) { int e = tid + 256 * i; rP[i] = e / 12; cP[i] = (e % 12) << 2; }

    float4 pg[12];
#pragma unroll
    for (int i = 0; i < 12; i++) pg[i] = *(const float4*)&pw[rP[i] * CH + cP[i]];
    {
        half* P0 = (half*)(sm + 99328);
#pragma unroll
        for (int i = 0; i < 12; i++) { half2* d = (half2*)&P0[rP[i] * 56 + cP[i]];
            d[0] = __floats2half2_rn(pg[i].x, pg[i].y); d[1] = __floats2half2_rn(pg[i].z, pg[i].w); }
    }

#pragma unroll 1
    for (int nc = 0; nc < 3; nc++) {
        float cfr[2][8][4];
#pragma unroll
        for (int mt = 0; mt < 2; mt++)
#pragma unroll
            for (int nt = 0; nt < 8; nt++)
#pragma unroll
                for (int q = 0; q < 4; q++) cfr[mt][nt][q] = 0.f;
#pragma unroll 1
        for (int ch2 = 0; ch2 < 16; ch2++) {
            int s = nc * 16 + ch2;
            __syncthreads();
            if (s < 47) {
                int s1 = s + 1; int nr = (s1 >> 4) * 256, ncol = (s1 & 15) * 48;
#pragma unroll
                for (int i = 0; i < 12; i++)
                    pg[i] = *(const float4*)&pw[(nr + rP[i]) * CH + ncol + cP[i]];
            }
            half* Pc = (half*)(sm + 99328 + (s & 1) * 28672);
#pragma unroll
            for (int kt = 0; kt < 3; kt++) {
                unsigned int afr[2][4], bfr[8][2];
                int l16 = lane & 15;
#pragma unroll
                for (int mt = 0; mt < 2; mt++)
                    ldm_x4(afr[mt], &Oh[(mw * 32 + mt * 16 + l16) * 776 + ch2 * 48 + kt * 16 + ((lane >> 4) << 3)]);
#pragma unroll
                for (int nt = 0; nt < 8; nt++)
                    ldm_x2(bfr[nt], &Pc[(nw * 64 + nt * 8 + (l16 & 7)) * 56 + kt * 16 + ((l16 >> 3) << 3)]);
#pragma unroll
                for (int mt = 0; mt < 2; mt++)
#pragma unroll
                    for (int nt = 0; nt < 8; nt++)
                        mma16816(cfr[mt][nt], afr[mt], bfr[nt]);
            }
            if (s < 47) {
                half* Pn = (half*)(sm + 99328 + ((s + 1) & 1) * 28672);
#pragma unroll
                for (int i = 0; i < 12; i++) { half2* d = (half2*)&Pn[rP[i] * 56 + cP[i]];
                    d[0] = __floats2half2_rn(pg[i].x, pg[i].y); d[1] = __floats2half2_rn(pg[i].z, pg[i].w); }
            }
        }
#pragma unroll
        for (int mt = 0; mt < 2; mt++)
#pragma unroll
            for (int nt = 0; nt < 8; nt++) {
                int row = mw * 32 + mt * 16 + (lane >> 2);
                int col = nc * 256 + nw * 64 + nt * 8 + ((lane & 3) << 1);
#pragma unroll
                for (int rr = 0; rr < 2; rr++) {
                    int gr = r0 + row + rr * 8;
                    if (gr < rowEnd) {
                        float2 st = make_float2(cfr[mt][nt][rr * 2] + bs[col],
                                                cfr[mt][nt][rr * 2 + 1] + bs[col + 1]);
                        *(float2*)&out[gr * CH + col] = st;
                    }
                }
            }
    }
}

// ---------------------------------------------------------------------------
extern "C" void kernel_launch(void* const* d_in, const int* in_sizes, int n_in,
                              void* d_out, int out_size) {
    const float* x = 0; const float* qkv_w = 0;
    const float* proj_w = 0; const float* proj_b = 0;
    for (int i = 0; i < n_in; i++) {
        int s = in_sizes[i];
        const float* p = (const float*)d_in[i];
        if (s == NTOK * CH)        { if (!x) x = p; }
        else if (s == 3 * CH * CH) { if (!qkv_w) qkv_w = p; }
        else if (s == CH * CH)     { if (!proj_w) proj_w = p; }
        else if (s == CH)          { if (!proj_b) proj_b = p; }
    }
    if (!x || !qkv_w || !proj_w || !proj_b) {
        x = (const float*)d_in[0]; qkv_w = (const float*)d_in[1];
        proj_w = (const float*)d_in[2]; proj_b = (const float*)d_in[3];
    }
    char* dout = (char*)d_out;

    static int done = 0;
    if (!done) {
        cudaFuncSetAttribute(qkv_kernel, cudaFuncAttributeMaxDynamicSharedMemorySize, 57344);
        cudaFuncSetAttribute(attn_kernel, cudaFuncAttributeMaxDynamicSharedMemorySize, 55296);
        cudaFuncSetAttribute(outproj_kernel, cudaFuncAttributeMaxDynamicSharedMemorySize, 159744);
        done = 1;
    }

    for (int grp = 0; grp < 2; grp++) {
        qkv_kernel<<<dim3(SEQ / 64, 24), 256, 57344>>>(x, qkv_w, dout, grp);
        attn_kernel<<<dim3(SEQ / 128, 24), 256, 55296>>>(dout, grp);
    }
    const int rs[9] = {0, 4096, 6144, 7168, 7680, 7936, 8064, 8128, 8192};
    for (int i = 0; i < 8; i++) {
        int a = rs[i], bnd = rs[i + 1];
        outproj_kernel<<<(bnd - a) / 64, 256, 159744>>>(proj_w, proj_b, dout, a, bnd);
    }
}

// round 14
// speedup vs baseline: 21.1767x; 1.6866x over previous
#include <cuda_runtime.h>
#include <cuda_fp16.h>
#include <cstdint>
#include <math.h>

#define Bq 4
#define SEQ 2048
#define CH 768
#define NH 12
#define HD 64
#define NTOK (Bq*SEQ)

#define KOFF 0
#define VOFF 6291456
#define QOFF 12582912

__device__ __forceinline__ void ldm_x4(unsigned int* r, const void* p) {
    unsigned int a = (unsigned int)__cvta_generic_to_shared(p);
    asm volatile("ldmatrix.sync.aligned.m8n8.x4.shared.b16 {%0,%1,%2,%3}, [%4];"
                 : "=r"(r[0]), "=r"(r[1]), "=r"(r[2]), "=r"(r[3]) : "r"(a));
}
__device__ __forceinline__ void ldm_x2(unsigned int* r, const void* p) {
    unsigned int a = (unsigned int)__cvta_generic_to_shared(p);
    asm volatile("ldmatrix.sync.aligned.m8n8.x2.shared.b16 {%0,%1}, [%2];"
                 : "=r"(r[0]), "=r"(r[1]) : "r"(a));
}
__device__ __forceinline__ void mma16816(float* c, const unsigned int* a,
                                         const unsigned int* b) {
    asm volatile("mma.sync.aligned.m16n8k16.row.col.f32.f16.f16.f32 "
                 "{%0,%1,%2,%3},{%4,%5,%6,%7},{%8,%9},{%0,%1,%2,%3};"
                 : "+f"(c[0]), "+f"(c[1]), "+f"(c[2]), "+f"(c[3])
                 : "r"(a[0]), "r"(a[1]), "r"(a[2]), "r"(a[3]), "r"(b[0]), "r"(b[1]));
}
__device__ __forceinline__ unsigned int pack_h2(float a, float b) {
    __half2 t = __floats2half2_rn(a, b);
    return *(unsigned int*)&t;
}

// ============ K1: QKV projection, one 6-head group (proven R12) ============
__global__ __launch_bounds__(256) void qkv_kernel(
    const float* __restrict__ x, const float* __restrict__ w,
    char* __restrict__ dout, int grp)
{
    extern __shared__ __align__(16) char sm[];
    int tid = threadIdx.x, warp = tid >> 5, lane = tid & 31;
    int mw = warp >> 2, nw = warp & 3;
    int t0 = blockIdx.x * 64;
    int bhg = blockIdx.y, b = bhg / 6, hg = bhg % 6, h = grp * 6 + hg;

    int rX[3], cX[3], rW[9], cW[9], wr[9];
#pragma unroll
    for (int i = 0; i < 3; i++) { int e = tid + 256 * i; rX[i] = e / 12; cX[i] = (e % 12) << 2; }
#pragma unroll
    for (int i = 0; i < 9; i++) {
        int e = tid + 256 * i; int r = e / 12; rW[i] = r; cW[i] = (e % 12) << 2;
        wr[i] = (r < 64) ? (h * HD + r) : (r < 128) ? (CH + h * HD + r - 64)
                                                    : (2 * CH + h * HD + r - 128);
    }

    float4 pX[3], pW[9];
#pragma unroll
    for (int i = 0; i < 3; i++) pX[i] = *(const float4*)&x[(b * SEQ + t0 + rX[i]) * CH + cX[i]];
#pragma unroll
    for (int i = 0; i < 9; i++) pW[i] = *(const float4*)&w[wr[i] * CH + cW[i]];
    {
        half* Xs = (half*)sm; half* Ws = (half*)(sm + 7168);
#pragma unroll
        for (int i = 0; i < 3; i++) { half2* d = (half2*)&Xs[rX[i] * 56 + cX[i]];
            d[0] = __floats2half2_rn(pX[i].x, pX[i].y); d[1] = __floats2half2_rn(pX[i].z, pX[i].w); }
#pragma unroll
        for (int i = 0; i < 9; i++) { half2* d = (half2*)&Ws[rW[i] * 56 + cW[i]];
            d[0] = __floats2half2_rn(pW[i].x, pW[i].y); d[1] = __floats2half2_rn(pW[i].z, pW[i].w); }
    }

    float cfr[2][6][4];
#pragma unroll
    for (int mt = 0; mt < 2; mt++)
#pragma unroll
        for (int nt = 0; nt < 6; nt++)
#pragma unroll
            for (int q = 0; q < 4; q++) cfr[mt][nt][q] = 0.f;

#pragma unroll 1
    for (int ch = 0; ch < 16; ch++) {
        __syncthreads();
        if (ch < 15) {
#pragma unroll
            for (int i = 0; i < 3; i++)
                pX[i] = *(const float4*)&x[(b * SEQ + t0 + rX[i]) * CH + (ch + 1) * 48 + cX[i]];
#pragma unroll
            for (int i = 0; i < 9; i++)
                pW[i] = *(const float4*)&w[wr[i] * CH + (ch + 1) * 48 + cW[i]];
        }
        half* Xc = (half*)(sm + (ch & 1) * 28672);
        half* Wc = (half*)(sm + (ch & 1) * 28672 + 7168);
#pragma unroll
        for (int kt = 0; kt < 3; kt++) {
            unsigned int afr[2][4], bfr[6][2];
            int l16 = lane & 15;
#pragma unroll
            for (int mt = 0; mt < 2; mt++)
                ldm_x4(afr[mt], &Xc[(mw * 32 + mt * 16 + l16) * 56 + kt * 16 + ((lane >> 4) << 3)]);
#pragma unroll
            for (int nt = 0; nt < 6; nt++)
                ldm_x2(bfr[nt], &Wc[(nw * 48 + nt * 8 + (l16 & 7)) * 56 + kt * 16 + ((l16 >> 3) << 3)]);
#pragma unroll
            for (int mt = 0; mt < 2; mt++)
#pragma unroll
                for (int nt = 0; nt < 6; nt++)
                    mma16816(cfr[mt][nt], afr[mt], bfr[nt]);
        }
        if (ch < 15) {
            half* Xn = (half*)(sm + ((ch + 1) & 1) * 28672);
            half* Wn = (half*)(sm + ((ch + 1) & 1) * 28672 + 7168);
#pragma unroll
            for (int i = 0; i < 3; i++) { half2* d = (half2*)&Xn[rX[i] * 56 + cX[i]];
                d[0] = __floats2half2_rn(pX[i].x, pX[i].y); d[1] = __floats2half2_rn(pX[i].z, pX[i].w); }
#pragma unroll
            for (int i = 0; i < 9; i++) { half2* d = (half2*)&Wn[rW[i] * 56 + cW[i]];
                d[0] = __floats2half2_rn(pW[i].x, pW[i].y); d[1] = __floats2half2_rn(pW[i].z, pW[i].w); }
        }
    }

    half* qoh = (half*)(dout + QOFF);
    half* kh  = (half*)(dout + KOFF);
    half* vth = (half*)(dout + VOFF);
#pragma unroll
    for (int mt = 0; mt < 2; mt++)
#pragma unroll
        for (int nt = 0; nt < 6; nt++) {
            int row = mw * 32 + mt * 16 + (lane >> 2);
            int col = nw * 48 + nt * 8 + ((lane & 3) << 1);
            int typ = col >> 6, dim = col & 63;
#pragma unroll
            for (int rr = 0; rr < 2; rr++) {
                int tok = t0 + row + rr * 8;
                float v0 = cfr[mt][nt][rr * 2], v1 = cfr[mt][nt][rr * 2 + 1];
                if (typ == 0) {
                    *(half2*)&qoh[(b * SEQ + tok) * CH + grp * 384 + hg * 64 + dim] =
                        __floats2half2_rn(v0 * 0.125f, v1 * 0.125f);
                } else if (typ == 1) {
                    *(half2*)&kh[(bhg * SEQ + tok) * 64 + dim] = __floats2half2_rn(v0, v1);
                } else {
                    vth[(bhg * 64 + dim) * SEQ + tok]     = __float2half(v0);
                    vth[(bhg * 64 + dim + 1) * SEQ + tok] = __float2half(v1);
                }
            }
        }
}

// ============ K2: attention (PROVEN R11/R12 code, unchanged) ============
__global__ __launch_bounds__(256) void attn_kernel(char* __restrict__ dout, int grp)
{
    extern __shared__ __align__(16) char sm[];
    half* Qs = (half*)sm;
    half* Kb[2] = { (half*)(sm + 18432), (half*)(sm + 27648) };
    half* Vb[2] = { (half*)(sm + 36864), (half*)(sm + 46080) };

    int tid = threadIdx.x, warp = tid >> 5, lane = tid & 31;
    int bhg = blockIdx.y, b = bhg / 6, hg = bhg % 6;
    int q0 = blockIdx.x * 128;
    half* qoh = (half*)(dout + QOFF);
    const half* kh  = (const half*)(dout + KOFF);
    const half* vth = (const half*)(dout + VOFF);

#pragma unroll
    for (int i = 0; i < 4; i++) {
        int e = tid + 256 * i; int r = e >> 3, c = e & 7;
        ((uint4*)&Qs[r * 72])[c] =
            ((const uint4*)&qoh[(b * SEQ + q0 + r) * CH + grp * 384 + hg * 64])[c];
    }
#pragma unroll
    for (int i = 0; i < 2; i++) {
        int e = tid + 256 * i; int r = e >> 3, c = e & 7;
        ((uint4*)&Kb[0][r * 72])[c] = ((const uint4*)&kh[(bhg * SEQ + r) * 64])[c];
        ((uint4*)&Vb[0][r * 72])[c] = ((const uint4*)&vth[(bhg * 64 + r) * SEQ])[c];
    }
    __syncthreads();

    unsigned int qA[4][4];
#pragma unroll
    for (int kt = 0; kt < 4; kt++)
        ldm_x4(qA[kt], &Qs[(warp * 16 + (lane & 15)) * 72 + kt * 16 + ((lane >> 4) << 3)]);

    float mrow[2] = {-1e30f, -1e30f}, lrow[2] = {0.f, 0.f}, ofr[8][4];
#pragma unroll
    for (int nt = 0; nt < 8; nt++)
#pragma unroll
        for (int q = 0; q < 4; q++) ofr[nt][q] = 0.f;

    int g = lane >> 3;
#pragma unroll 1
    for (int it = 0; it < 32; it++) {
        __syncthreads();
        uint4 pk[2], pv[2];
        if (it < 31) {
            int kb2 = (it + 1) * 64;
#pragma unroll
            for (int i = 0; i < 2; i++) {
                int e = tid + 256 * i; int r = e >> 3, c = e & 7;
                pk[i] = ((const uint4*)&kh[(bhg * SEQ + kb2 + r) * 64])[c];
                pv[i] = ((const uint4*)&vth[(bhg * 64 + r) * SEQ + kb2])[c];
            }
        }
        half* Kc = Kb[it & 1]; half* Vc = Vb[it & 1];

        float sfr[8][4];
#pragma unroll
        for (int nt = 0; nt < 8; nt++)
#pragma unroll
            for (int q = 0; q < 4; q++) sfr[nt][q] = 0.f;
#pragma unroll
        for (int kt = 0; kt < 4; kt++) {
            unsigned int bfr[8][2];
#pragma unroll
            for (int np = 0; np < 4; np++) {
                unsigned int r4[4];
                ldm_x4(r4, &Kc[(np * 16 + (g & 1) * 8 + (lane & 7)) * 72 + kt * 16 + ((g >> 1) << 3)]);
                bfr[2 * np][0] = r4[0];     bfr[2 * np][1] = r4[2];
                bfr[2 * np + 1][0] = r4[1]; bfr[2 * np + 1][1] = r4[3];
            }
#pragma unroll
            for (int nt = 0; nt < 8; nt++) mma16816(sfr[nt], qA[kt], bfr[nt]);
        }
#pragma unroll
        for (int hf = 0; hf < 2; hf++) {
            float mx = mrow[hf];
#pragma unroll
            for (int nt = 0; nt < 8; nt++)
                mx = fmaxf(mx, fmaxf(sfr[nt][hf * 2], sfr[nt][hf * 2 + 1]));
            mx = fmaxf(mx, __shfl_xor_sync(0xffffffffu, mx, 1));
            mx = fmaxf(mx, __shfl_xor_sync(0xffffffffu, mx, 2));
            float c = __expf(mrow[hf] - mx); mrow[hf] = mx;
            float sum = 0.f;
#pragma unroll
            for (int nt = 0; nt < 8; nt++) {
                float p0 = __expf(sfr[nt][hf * 2] - mx);
                float p1 = __expf(sfr[nt][hf * 2 + 1] - mx);
                sfr[nt][hf * 2] = p0; sfr[nt][hf * 2 + 1] = p1; sum += p0 + p1;
            }
            sum += __shfl_xor_sync(0xffffffffu, sum, 1);
            sum += __shfl_xor_sync(0xffffffffu, sum, 2);
            lrow[hf] = lrow[hf] * c + sum;
#pragma unroll
            for (int nt = 0; nt < 8; nt++) {
                ofr[nt][hf * 2] *= c; ofr[nt][hf * 2 + 1] *= c;
            }
        }
        unsigned int pA[4][4];
#pragma unroll
        for (int kt = 0; kt < 4; kt++) {
            pA[kt][0] = pack_h2(sfr[2 * kt][0], sfr[2 * kt][1]);
            pA[kt][1] = pack_h2(sfr[2 * kt][2], sfr[2 * kt][3]);
            pA[kt][2] = pack_h2(sfr[2 * kt + 1][0], sfr[2 * kt + 1][1]);
            pA[kt][3] = pack_h2(sfr[2 * kt + 1][2], sfr[2 * kt + 1][3]);
        }
#pragma unroll
        for (int kt = 0; kt < 4; kt++) {
            unsigned int bfr[8][2];
#pragma unroll
            for (int np = 0; np < 4; np++) {
                unsigned int r4[4];
                ldm_x4(r4, &Vc[(np * 16 + (g & 1) * 8 + (lane & 7)) * 72 + kt * 16 + ((g >> 1) << 3)]);
                bfr[2 * np][0] = r4[0];     bfr[2 * np][1] = r4[2];
                bfr[2 * np + 1][0] = r4[1]; bfr[2 * np + 1][1] = r4[3];
            }
#pragma unroll
            for (int nt = 0; nt < 8; nt++) mma16816(ofr[nt], pA[kt], bfr[nt]);
        }
        if (it < 31) {
            half* Kn = Kb[(it + 1) & 1]; half* Vn = Vb[(it + 1) & 1];
#pragma unroll
            for (int i = 0; i < 2; i++) {
                int e = tid + 256 * i; int r = e >> 3, c = e & 7;
                ((uint4*)&Kn[r * 72])[c] = pk[i];
                ((uint4*)&Vn[r * 72])[c] = pv[i];
            }
        }
    }

    float inv[2] = {1.0f / lrow[0], 1.0f / lrow[1]};
#pragma unroll
    for (int nt = 0; nt < 8; nt++) {
        int row = warp * 16 + (lane >> 2);
        int col = nt * 8 + ((lane & 3) << 1);
#pragma unroll
        for (int rr = 0; rr < 2; rr++) {
            int gt = b * SEQ + q0 + row + rr * 8;
            *(half2*)&qoh[gt * CH + grp * 384 + hg * 64 + col] =
                __floats2half2_rn(ofr[nt][rr * 2] * inv[rr], ofr[nt][rr * 2 + 1] * inv[rr]);
        }
    }
}

// ============ K3: out-proj, 64x64 tiles (col-split cascade) ============
// grid = (rows/64, 12). CTA: out rows [r0,r0+64) x cols [c0,c0+64).
__global__ __launch_bounds__(256) void outproj_kernel(
    const float* __restrict__ pw, const float* __restrict__ bias,
    char* __restrict__ dout, int rowBeg, int rowEnd)
{
    extern __shared__ __align__(16) char sm[];
    half*  Oh = (half*)sm;                 // [64][776] = 99328 B
    // Pw bufs at sm+99328 + buf*7168, each [64][56]
    float* bs = (float*)(sm + 113664);     // [64]

    int tid = threadIdx.x, warp = tid >> 5, lane = tid & 31;
    int mw = warp >> 2, nw = warp & 3;     // 2 row-groups x 4 col-groups
    int r0 = rowBeg + blockIdx.x * 64;
    int c0 = blockIdx.y * 64;
    const half* qo = (const half*)(dout + QOFF);
    float* out = (float*)dout;

    // Stage this CTA's O tile FIRST — FULL 768-wide rows (GEMM k-dim!)
#pragma unroll
    for (int i = 0; i < 24; i++) {
        int e = tid + 256 * i; int r = e / 96, c = e % 96;
        int rr = r0 + r; if (rr > NTOK - 1) rr = NTOK - 1;
        ((uint4*)&Oh[r * 776])[c] = ((const uint4*)&qo[rr * CH])[c];
    }
    if (tid < 64) bs[tid] = bias[c0 + tid];

    int rP[3], cP[3];
#pragma unroll
    for (int i = 0; i < 3; i++) { int e = tid + 256 * i; rP[i] = e / 12; cP[i] = (e % 12) << 2; }

    float4 pg[3];
#pragma unroll
    for (int i = 0; i < 3; i++) pg[i] = *(const float4*)&pw[(c0 + rP[i]) * CH + cP[i]];
    {
        half* P0 = (half*)(sm + 99328);
#pragma unroll
        for (int i = 0; i < 3; i++) { half2* d = (half2*)&P0[rP[i] * 56 + cP[i]];
            d[0] = __floats2half2_rn(pg[i].x, pg[i].y); d[1] = __floats2half2_rn(pg[i].z, pg[i].w); }
    }

    float cfr[2][2][4];
#pragma unroll
    for (int mt = 0; mt < 2; mt++)
#pragma unroll
        for (int nt = 0; nt < 2; nt++)
#pragma unroll
            for (int q = 0; q < 4; q++) cfr[mt][nt][q] = 0.f;

#pragma unroll 1
    for (int s = 0; s < 16; s++) {
        __syncthreads();
        if (s < 15) {
#pragma unroll
            for (int i = 0; i < 3; i++)
                pg[i] = *(const float4*)&pw[(c0 + rP[i]) * CH + (s + 1) * 48 + cP[i]];
        }
        half* Pc = (half*)(sm + 99328 + (s & 1) * 7168);
#pragma unroll
        for (int kt = 0; kt < 3; kt++) {
            unsigned int afr[2][4], bfr[2][2];
            int l16 = lane & 15;
#pragma unroll
            for (int mt = 0; mt < 2; mt++)
                ldm_x4(afr[mt], &Oh[(mw * 32 + mt * 16 + l16) * 776 + s * 48 + kt * 16 + ((lane >> 4) << 3)]);
#pragma unroll
            for (int nt = 0; nt < 2; nt++)
                ldm_x2(bfr[nt], &Pc[(nw * 16 + nt * 8 + (l16 & 7)) * 56 + kt * 16 + ((l16 >> 3) << 3)]);
#pragma unroll
            for (int mt = 0; mt < 2; mt++)
#pragma unroll
                for (int nt = 0; nt < 2; nt++)
                    mma16816(cfr[mt][nt], afr[mt], bfr[nt]);
        }
        if (s < 15) {
            half* Pn = (half*)(sm + 99328 + ((s + 1) & 1) * 7168);
#pragma unroll
            for (int i = 0; i < 3; i++) { half2* d = (half2*)&Pn[rP[i] * 56 + cP[i]];
                d[0] = __floats2half2_rn(pg[i].x, pg[i].y); d[1] = __floats2half2_rn(pg[i].z, pg[i].w); }
        }
    }

#pragma unroll
    for (int mt = 0; mt < 2; mt++)
#pragma unroll
        for (int nt = 0; nt < 2; nt++) {
            int row = mw * 32 + mt * 16 + (lane >> 2);
            int col = nw * 16 + nt * 8 + ((lane & 3) << 1);
#pragma unroll
            for (int rr = 0; rr < 2; rr++) {
                int gr = r0 + row + rr * 8;
                if (gr < rowEnd) {
                    float2 st = make_float2(cfr[mt][nt][rr * 2] + bs[col],
                                            cfr[mt][nt][rr * 2 + 1] + bs[col + 1]);
                    *(float2*)&out[gr * CH + c0 + col] = st;
                }
            }
        }
}

// ---------------------------------------------------------------------------
extern "C" void kernel_launch(void* const* d_in, const int* in_sizes, int n_in,
                              void* d_out, int out_size) {
    const float* x = 0; const float* qkv_w = 0;
    const float* proj_w = 0; const float* proj_b = 0;
    for (int i = 0; i < n_in; i++) {
        int s = in_sizes[i];
        const float* p = (const float*)d_in[i];
        if (s == NTOK * CH)        { if (!x) x = p; }
        else if (s == 3 * CH * CH) { if (!qkv_w) qkv_w = p; }
        else if (s == CH * CH)     { if (!proj_w) proj_w = p; }
        else if (s == CH)          { if (!proj_b) proj_b = p; }
    }
    if (!x || !qkv_w || !proj_w || !proj_b) {
        x = (const float*)d_in[0]; qkv_w = (const float*)d_in[1];
        proj_w = (const float*)d_in[2]; proj_b = (const float*)d_in[3];
    }
    char* dout = (char*)d_out;

    static int done = 0;
    if (!done) {
        cudaFuncSetAttribute(qkv_kernel, cudaFuncAttributeMaxDynamicSharedMemorySize, 57344);
        cudaFuncSetAttribute(attn_kernel, cudaFuncAttributeMaxDynamicSharedMemorySize, 55296);
        cudaFuncSetAttribute(outproj_kernel, cudaFuncAttributeMaxDynamicSharedMemorySize, 113920);
        done = 1;
    }

    for (int grp = 0; grp < 2; grp++) {
        qkv_kernel<<<dim3(SEQ / 64, 24), 256, 57344>>>(x, qkv_w, dout, grp);
        attn_kernel<<<dim3(SEQ / 128, 24), 256, 55296>>>(dout, grp);
    }
    const int rs[9] = {0, 4096, 6144, 7168, 7680, 7936, 8064, 8128, 8192};
    for (int i = 0; i < 8; i++) {
        int a = rs[i], bnd = rs[i + 1];
        outproj_kernel<<<dim3((bnd - a) / 64, 12), 256, 113920>>>(proj_w, proj_b, dout, a, bnd);
    }
}